// round 1
// baseline (speedup 1.0000x reference)
#include <cuda_runtime.h>
#include <math.h>

#define T_TOK 8192
#define H_DIM 1024
#define F_DIM 4096
#define E_NUM 8
#define N_SLOTS (T_TOK * 2)

// ---------------- scratch (device globals; no runtime allocation) ----------------
__device__ float g_probs[T_TOK * E_NUM];
__device__ float g_lse2[T_TOK];
__device__ int   g_tok_e[T_TOK * 2];
__device__ float g_tok_w[T_TOK * 2];
__device__ int   g_count[E_NUM];
__device__ int   g_off[E_NUM + 1];
__device__ int   g_cursor[E_NUM];
__device__ int   g_slot_tok[N_SLOTS];
__device__ float g_slot_w[N_SLOTS];
__device__ float g_h[(size_t)N_SLOTS * F_DIM];   // 256 MB fp32 intermediate

// ---------------- init: zero output + counters ----------------
__global__ void init_kernel(float* out, int n) {
    int tid = blockIdx.x * blockDim.x + threadIdx.x;
    if (tid < E_NUM) { g_count[tid] = 0; g_cursor[tid] = 0; }
    for (int i = tid; i < n; i += gridDim.x * blockDim.x) out[i] = 0.f;
}

// ---------------- router: one warp per token ----------------
__global__ void router_kernel(const float* __restrict__ x, const float* __restrict__ gw) {
    __shared__ float sgw[H_DIM * E_NUM];  // 32 KB
    for (int i = threadIdx.x; i < H_DIM * E_NUM; i += blockDim.x) sgw[i] = gw[i];
    __syncthreads();

    int warp = threadIdx.x >> 5;
    int lane = threadIdx.x & 31;
    int t = blockIdx.x * (blockDim.x >> 5) + warp;
    if (t >= T_TOK) return;

    const float* xr = x + (size_t)t * H_DIM;
    float acc[E_NUM];
#pragma unroll
    for (int e = 0; e < E_NUM; e++) acc[e] = 0.f;

    for (int h = lane; h < H_DIM; h += 32) {
        float xv = xr[h];
#pragma unroll
        for (int e = 0; e < E_NUM; e++) acc[e] += xv * sgw[h * E_NUM + e];
    }
#pragma unroll
    for (int off = 16; off; off >>= 1) {
#pragma unroll
        for (int e = 0; e < E_NUM; e++)
            acc[e] += __shfl_xor_sync(0xffffffffu, acc[e], off);
    }

    if (lane == 0) {
        float m = acc[0];
#pragma unroll
        for (int e = 1; e < E_NUM; e++) m = fmaxf(m, acc[e]);
        float p[E_NUM], s = 0.f;
#pragma unroll
        for (int e = 0; e < E_NUM; e++) { p[e] = expf(acc[e] - m); s += p[e]; }
        float lse = m + logf(s);
        g_lse2[t] = lse * lse;
        float inv = 1.f / s;
#pragma unroll
        for (int e = 0; e < E_NUM; e++) { p[e] *= inv; g_probs[t * E_NUM + e] = p[e]; }

        // top-2 (ties -> lowest index, matching lax.top_k)
        int i1 = 0;
#pragma unroll
        for (int e = 1; e < E_NUM; e++) if (p[e] > p[i1]) i1 = e;
        int i2 = (i1 == 0) ? 1 : 0;
#pragma unroll
        for (int e = 0; e < E_NUM; e++)
            if (e != i1 && p[e] > p[i2]) i2 = e;

        float w1 = p[i1], w2 = p[i2];
        float ws = 1.f / (w1 + w2);
        g_tok_e[2 * t + 0] = i1;  g_tok_w[2 * t + 0] = w1 * ws;
        g_tok_e[2 * t + 1] = i2;  g_tok_w[2 * t + 1] = w2 * ws;
        atomicAdd(&g_count[i1], 1);
        atomicAdd(&g_count[i2], 1);
    }
}

// ---------------- exclusive prefix over E=8 counts ----------------
__global__ void offsets_kernel() {
    g_off[0] = 0;
    for (int e = 0; e < E_NUM; e++) g_off[e + 1] = g_off[e] + g_count[e];
}

// ---------------- scatter tokens into per-expert slot lists ----------------
__global__ void scatter_kernel() {
    int t = blockIdx.x * blockDim.x + threadIdx.x;
    if (t >= T_TOK) return;
#pragma unroll
    for (int k = 0; k < 2; k++) {
        int e = g_tok_e[2 * t + k];
        int pos = g_off[e] + atomicAdd(&g_cursor[e], 1);
        g_slot_tok[pos] = t;
        g_slot_w[pos] = g_tok_w[2 * t + k];
    }
}

// ---------------- deterministic loss reduction ----------------
__global__ void reduce_kernel(float* out, int out_size) {
    __shared__ float sp[256 * E_NUM];
    __shared__ float sl[256];
    int tid = threadIdx.x;
    float lp[E_NUM];
#pragma unroll
    for (int e = 0; e < E_NUM; e++) lp[e] = 0.f;
    float ll = 0.f;
    for (int t = tid; t < T_TOK; t += 256) {
#pragma unroll
        for (int e = 0; e < E_NUM; e++) lp[e] += g_probs[t * E_NUM + e];
        ll += g_lse2[t];
    }
#pragma unroll
    for (int e = 0; e < E_NUM; e++) sp[tid * E_NUM + e] = lp[e];
    sl[tid] = ll;
    __syncthreads();
    for (int s = 128; s; s >>= 1) {
        if (tid < s) {
#pragma unroll
            for (int e = 0; e < E_NUM; e++)
                sp[tid * E_NUM + e] += sp[(tid + s) * E_NUM + e];
            sl[tid] += sl[tid + s];
        }
        __syncthreads();
    }
    if (tid == 0) {
        float bal = 0.f;
        for (int e = 0; e < E_NUM; e++) {
            float frac = (float)g_count[e] / (float)(T_TOK * 2);
            float meanp = sp[e] / (float)T_TOK;
            bal += frac * meanp;
        }
        out[out_size - 2] = bal * (float)E_NUM;
        out[out_size - 1] = sl[0] / (float)T_TOK;
    }
}

// ---------------- pass A: h = silu(X Wg) * (X Wu), gathered rows ----------------
// tile M=64, N=128, K=16; 256 threads, each computes 4x8 of both outputs
__global__ void __launch_bounds__(256, 2)
gemm_gateup_kernel(const float* __restrict__ x,
                   const float* __restrict__ wg,
                   const float* __restrict__ wu) {
    int e = blockIdx.z;
    int cnt = g_count[e];
    int m0 = blockIdx.y * 64;
    if (m0 >= cnt) return;
    int base = g_off[e];
    int n0 = blockIdx.x * 128;

    __shared__ float sA[16][64];
    __shared__ float sBg[16][128];
    __shared__ float sBu[16][128];
    __shared__ int toks[64];

    int tid = threadIdx.x;
    if (tid < 64) toks[tid] = (m0 + tid < cnt) ? g_slot_tok[base + m0 + tid] : -1;
    __syncthreads();

    const float* Wg = wg + (size_t)e * H_DIM * F_DIM;
    const float* Wu = wu + (size_t)e * H_DIM * F_DIM;

    float accG[4][8], accU[4][8];
#pragma unroll
    for (int i = 0; i < 4; i++)
#pragma unroll
        for (int j = 0; j < 8; j++) { accG[i][j] = 0.f; accU[i][j] = 0.f; }

    int tx = tid & 15, ty = tid >> 4;
    int ar = tid >> 2, ac = (tid & 3) * 4;
    int tokA = toks[ar];

    for (int k0 = 0; k0 < H_DIM; k0 += 16) {
        float4 av = make_float4(0.f, 0.f, 0.f, 0.f);
        if (tokA >= 0) av = *(const float4*)(x + (size_t)tokA * H_DIM + k0 + ac);
        sA[ac + 0][ar] = av.x; sA[ac + 1][ar] = av.y;
        sA[ac + 2][ar] = av.z; sA[ac + 3][ar] = av.w;
#pragma unroll
        for (int rep = 0; rep < 2; rep++) {
            int lin = tid + rep * 256;
            int row = lin >> 5, c4 = (lin & 31) * 4;
            *(float4*)&sBg[row][c4] = *(const float4*)(Wg + (size_t)(k0 + row) * F_DIM + n0 + c4);
            *(float4*)&sBu[row][c4] = *(const float4*)(Wu + (size_t)(k0 + row) * F_DIM + n0 + c4);
        }
        __syncthreads();
#pragma unroll
        for (int kk = 0; kk < 16; kk++) {
            float a[4];
#pragma unroll
            for (int i = 0; i < 4; i++) a[i] = sA[kk][ty * 4 + i];
            float bg[8], bu[8];
            *(float4*)&bg[0] = *(float4*)&sBg[kk][tx * 8];
            *(float4*)&bg[4] = *(float4*)&sBg[kk][tx * 8 + 4];
            *(float4*)&bu[0] = *(float4*)&sBu[kk][tx * 8];
            *(float4*)&bu[4] = *(float4*)&sBu[kk][tx * 8 + 4];
#pragma unroll
            for (int i = 0; i < 4; i++)
#pragma unroll
                for (int j = 0; j < 8; j++) {
                    accG[i][j] += a[i] * bg[j];
                    accU[i][j] += a[i] * bu[j];
                }
        }
        __syncthreads();
    }

#pragma unroll
    for (int i = 0; i < 4; i++) {
        int r = ty * 4 + i;
        if (m0 + r < cnt) {
            int slot = base + m0 + r;
            float* hp = g_h + (size_t)slot * F_DIM + n0 + tx * 8;
#pragma unroll
            for (int j = 0; j < 8; j++) {
                float g = accG[i][j];
                float s = g / (1.f + __expf(-g));   // silu
                hp[j] = s * accU[i][j];
            }
        }
    }
}

// ---------------- pass B: out += w * (H1 Wd), atomic combine ----------------
__global__ void __launch_bounds__(256, 2)
gemm_down_kernel(const float* __restrict__ wd, float* __restrict__ out) {
    int e = blockIdx.z;
    int cnt = g_count[e];
    int m0 = blockIdx.y * 64;
    if (m0 >= cnt) return;
    int base = g_off[e];
    int n0 = blockIdx.x * 128;

    __shared__ float sA[16][64];
    __shared__ float sB[16][128];

    const float* Wd = wd + (size_t)e * F_DIM * H_DIM;
    float acc[4][8];
#pragma unroll
    for (int i = 0; i < 4; i++)
#pragma unroll
        for (int j = 0; j < 8; j++) acc[i][j] = 0.f;

    int tid = threadIdx.x, tx = tid & 15, ty = tid >> 4;
    int ar = tid >> 2, ac = (tid & 3) * 4;
    const float* arow = (m0 + ar < cnt) ? g_h + (size_t)(base + m0 + ar) * F_DIM : nullptr;

    for (int k0 = 0; k0 < F_DIM; k0 += 16) {
        float4 av = make_float4(0.f, 0.f, 0.f, 0.f);
        if (arow) av = *(const float4*)(arow + k0 + ac);
        sA[ac + 0][ar] = av.x; sA[ac + 1][ar] = av.y;
        sA[ac + 2][ar] = av.z; sA[ac + 3][ar] = av.w;
#pragma unroll
        for (int rep = 0; rep < 2; rep++) {
            int lin = tid + rep * 256;
            int row = lin >> 5, c4 = (lin & 31) * 4;
            *(float4*)&sB[row][c4] = *(const float4*)(Wd + (size_t)(k0 + row) * H_DIM + n0 + c4);
        }
        __syncthreads();
#pragma unroll
        for (int kk = 0; kk < 16; kk++) {
            float a[4];
#pragma unroll
            for (int i = 0; i < 4; i++) a[i] = sA[kk][ty * 4 + i];
            float b[8];
            *(float4*)&b[0] = *(float4*)&sB[kk][tx * 8];
            *(float4*)&b[4] = *(float4*)&sB[kk][tx * 8 + 4];
#pragma unroll
            for (int i = 0; i < 4; i++)
#pragma unroll
                for (int j = 0; j < 8; j++) acc[i][j] += a[i] * b[j];
        }
        __syncthreads();
    }

#pragma unroll
    for (int i = 0; i < 4; i++) {
        int r = ty * 4 + i;
        if (m0 + r < cnt) {
            int slot = base + m0 + r;
            int tok = g_slot_tok[slot];
            float w = g_slot_w[slot];
            float* op = out + (size_t)tok * H_DIM + n0 + tx * 8;
#pragma unroll
            for (int j = 0; j < 8; j++) atomicAdd(&op[j], w * acc[i][j]);
        }
    }
}

// ---------------- launch ----------------
extern "C" void kernel_launch(void* const* d_in, const int* in_sizes, int n_in,
                              void* d_out, int out_size) {
    const float* x  = (const float*)d_in[0];
    const float* gw = (const float*)d_in[1];
    const float* wg = (const float*)d_in[2];
    const float* wu = (const float*)d_in[3];
    const float* wd = (const float*)d_in[4];
    float* out = (float*)d_out;

    init_kernel<<<512, 256>>>(out, out_size);
    router_kernel<<<T_TOK / 8, 256>>>(x, gw);
    offsets_kernel<<<1, 1>>>();
    scatter_kernel<<<T_TOK / 256, 256>>>();
    reduce_kernel<<<1, 256>>>(out, out_size);

    dim3 gA(F_DIM / 128, 128, E_NUM);
    gemm_gateup_kernel<<<gA, 256>>>(x, wg, wu);

    dim3 gB(H_DIM / 128, 128, E_NUM);
    gemm_down_kernel<<<gB, 256>>>(wd, out);
}

// round 3
// speedup vs baseline: 4.1879x; 4.1879x over previous
#include <cuda_runtime.h>
#include <math.h>
#include <stdint.h>

#define T_TOK 8192
#define H_DIM 1024
#define F_DIM 4096
#define E_NUM 8
#define N_SLOTS (T_TOK * 2)

// ---------------- scratch (device globals; no runtime allocation) ----------------
__device__ float g_probs[T_TOK * E_NUM];
__device__ float g_lse2[T_TOK];
__device__ int   g_tok_e[T_TOK * 2];
__device__ float g_tok_w[T_TOK * 2];
__device__ int   g_count[E_NUM];
__device__ int   g_off[E_NUM + 1];
__device__ int   g_cursor[E_NUM];
__device__ int   g_slot_tok[N_SLOTS];
__device__ float g_slot_w[N_SLOTS];
__device__ float g_h[(size_t)N_SLOTS * F_DIM];   // 256 MB fp32 intermediate

// ---------------- helpers ----------------
__device__ __forceinline__ uint32_t f2tf(float f) {
    uint32_t r;
    asm("cvt.rna.tf32.f32 %0, %1;" : "=r"(r) : "f"(f));
    return r;
}
__device__ __forceinline__ uint4 cvt4(float4 v) {
    uint4 u; u.x = f2tf(v.x); u.y = f2tf(v.y); u.z = f2tf(v.z); u.w = f2tf(v.w);
    return u;
}
__device__ __forceinline__ void mma_tf32(float* c, const uint32_t* a, const uint32_t* b) {
    asm volatile("mma.sync.aligned.m16n8k8.row.col.f32.tf32.tf32.f32 "
                 "{%0,%1,%2,%3}, {%4,%5,%6,%7}, {%8,%9}, {%0,%1,%2,%3};"
                 : "+f"(c[0]), "+f"(c[1]), "+f"(c[2]), "+f"(c[3])
                 : "r"(a[0]), "r"(a[1]), "r"(a[2]), "r"(a[3]), "r"(b[0]), "r"(b[1]));
}
__device__ __forceinline__ float silu_mul(float g, float u) {
    return g / (1.f + __expf(-g)) * u;
}

// ---------------- init ----------------
__global__ void init_kernel(float* out, int n) {
    int tid = blockIdx.x * blockDim.x + threadIdx.x;
    if (tid < E_NUM) { g_count[tid] = 0; g_cursor[tid] = 0; }
    for (int i = tid; i < n; i += gridDim.x * blockDim.x) out[i] = 0.f;
}

// ---------------- router: one warp per token ----------------
__global__ void router_kernel(const float* __restrict__ x, const float* __restrict__ gw) {
    __shared__ float sgw[H_DIM * E_NUM];
    for (int i = threadIdx.x; i < H_DIM * E_NUM; i += blockDim.x) sgw[i] = gw[i];
    __syncthreads();

    int warp = threadIdx.x >> 5;
    int lane = threadIdx.x & 31;
    int t = blockIdx.x * (blockDim.x >> 5) + warp;
    if (t >= T_TOK) return;

    const float* xr = x + (size_t)t * H_DIM;
    float acc[E_NUM];
#pragma unroll
    for (int e = 0; e < E_NUM; e++) acc[e] = 0.f;
    for (int h = lane; h < H_DIM; h += 32) {
        float xv = xr[h];
#pragma unroll
        for (int e = 0; e < E_NUM; e++) acc[e] += xv * sgw[h * E_NUM + e];
    }
#pragma unroll
    for (int off = 16; off; off >>= 1)
#pragma unroll
        for (int e = 0; e < E_NUM; e++) acc[e] += __shfl_xor_sync(0xffffffffu, acc[e], off);

    if (lane == 0) {
        float m = acc[0];
#pragma unroll
        for (int e = 1; e < E_NUM; e++) m = fmaxf(m, acc[e]);
        float p[E_NUM], s = 0.f;
#pragma unroll
        for (int e = 0; e < E_NUM; e++) { p[e] = expf(acc[e] - m); s += p[e]; }
        float lse = m + logf(s);
        g_lse2[t] = lse * lse;
        float inv = 1.f / s;
#pragma unroll
        for (int e = 0; e < E_NUM; e++) { p[e] *= inv; g_probs[t * E_NUM + e] = p[e]; }
        int i1 = 0;
#pragma unroll
        for (int e = 1; e < E_NUM; e++) if (p[e] > p[i1]) i1 = e;
        int i2 = (i1 == 0) ? 1 : 0;
#pragma unroll
        for (int e = 0; e < E_NUM; e++) if (e != i1 && p[e] > p[i2]) i2 = e;
        float w1 = p[i1], w2 = p[i2];
        float ws = 1.f / (w1 + w2);
        g_tok_e[2 * t + 0] = i1;  g_tok_w[2 * t + 0] = w1 * ws;
        g_tok_e[2 * t + 1] = i2;  g_tok_w[2 * t + 1] = w2 * ws;
        atomicAdd(&g_count[i1], 1);
        atomicAdd(&g_count[i2], 1);
    }
}

__global__ void offsets_kernel() {
    g_off[0] = 0;
    for (int e = 0; e < E_NUM; e++) g_off[e + 1] = g_off[e] + g_count[e];
}

__global__ void scatter_kernel() {
    int t = blockIdx.x * blockDim.x + threadIdx.x;
    if (t >= T_TOK) return;
#pragma unroll
    for (int k = 0; k < 2; k++) {
        int e = g_tok_e[2 * t + k];
        int pos = g_off[e] + atomicAdd(&g_cursor[e], 1);
        g_slot_tok[pos] = t;
        g_slot_w[pos] = g_tok_w[2 * t + k];
    }
}

__global__ void reduce_kernel(float* out, int out_size) {
    __shared__ float sp[256 * E_NUM];
    __shared__ float sl[256];
    int tid = threadIdx.x;
    float lp[E_NUM];
#pragma unroll
    for (int e = 0; e < E_NUM; e++) lp[e] = 0.f;
    float ll = 0.f;
    for (int t = tid; t < T_TOK; t += 256) {
#pragma unroll
        for (int e = 0; e < E_NUM; e++) lp[e] += g_probs[t * E_NUM + e];
        ll += g_lse2[t];
    }
#pragma unroll
    for (int e = 0; e < E_NUM; e++) sp[tid * E_NUM + e] = lp[e];
    sl[tid] = ll;
    __syncthreads();
    for (int s = 128; s; s >>= 1) {
        if (tid < s) {
#pragma unroll
            for (int e = 0; e < E_NUM; e++) sp[tid * E_NUM + e] += sp[(tid + s) * E_NUM + e];
            sl[tid] += sl[tid + s];
        }
        __syncthreads();
    }
    if (tid == 0) {
        float bal = 0.f;
        for (int e = 0; e < E_NUM; e++) {
            float frac = (float)g_count[e] / (float)(T_TOK * 2);
            float meanp = sp[e] / (float)T_TOK;
            bal += frac * meanp;
        }
        out[out_size - 2] = bal * (float)E_NUM;
        out[out_size - 1] = sl[0] / (float)T_TOK;
    }
}

// ================= pass A: h = silu(X Wg) * (X Wu), tf32 mma.sync ================
// CTA tile 128(M) x 128(N), BK=16; 8 warps: wm = wid&1 (2x64), wn = wid>>1 (4x32)
// SMEM: A m-major stride 20 words; B k-major stride 136 words (conflict-free frags)
#define SA 20
#define SBA 136
#define A_WORDS (128 * SA)        // 2560
#define BG_OFF  A_WORDS           // 2560
#define BU_OFF  (A_WORDS + 16 * SBA)  // 4736
#define STG_A   (A_WORDS + 2 * 16 * SBA) // 6912 words per stage
#define SMEM_A_BYTES (512 + 2 * STG_A * 4)

__global__ void __launch_bounds__(256, 1)
gemmA_kernel(const float* __restrict__ x,
             const float* __restrict__ wg,
             const float* __restrict__ wu) {
    int e = blockIdx.z;
    int cnt = g_count[e];
    int m0 = blockIdx.y * 128;
    if (m0 >= cnt) return;
    int base = g_off[e];
    int n0 = blockIdx.x * 128;

    extern __shared__ __align__(16) char smem_raw[];
    int* toks_s = (int*)smem_raw;
    uint32_t* buf = (uint32_t*)(smem_raw + 512);

    int tid = threadIdx.x, wid = tid >> 5, lane = tid & 31;
    int gid = lane >> 2, tig = lane & 3;
    int mbase = (wid & 1) * 64;
    int nbase = (wid >> 1) * 32;

    if (tid < 128) {
        int idx = m0 + tid;
        toks_s[tid] = (idx < cnt) ? g_slot_tok[base + idx] : -1;
    }
    __syncthreads();

    const float* Wg = wg + (size_t)e * H_DIM * F_DIM + n0;
    const float* Wu = wu + (size_t)e * H_DIM * F_DIM + n0;

    float accG[4][4][4], accU[4][4][4];
#pragma unroll
    for (int mt = 0; mt < 4; mt++)
#pragma unroll
        for (int nt = 0; nt < 4; nt++)
#pragma unroll
            for (int i = 0; i < 4; i++) { accG[mt][nt][i] = 0.f; accU[mt][nt][i] = 0.f; }

    // staging index precompute
    int ar[2], akq[2], bkk[2], bnq[2];
#pragma unroll
    for (int i = 0; i < 2; i++) {
        int idx = tid + i * 256;
        ar[i] = idx >> 2;  akq[i] = idx & 3;
        bkk[i] = idx >> 5; bnq[i] = idx & 31;
    }

    float4 pa[2], pg[2], pu[2];
    const float4 z4 = make_float4(0.f, 0.f, 0.f, 0.f);

    // prefetch chunk 0
#pragma unroll
    for (int i = 0; i < 2; i++) {
        int tok = toks_s[ar[i]];
        pa[i] = (tok >= 0) ? *(const float4*)(x + (size_t)tok * H_DIM + akq[i] * 4) : z4;
        pg[i] = *(const float4*)(Wg + (size_t)bkk[i] * F_DIM + bnq[i] * 4);
        pu[i] = *(const float4*)(Wu + (size_t)bkk[i] * F_DIM + bnq[i] * 4);
    }
#pragma unroll
    for (int i = 0; i < 2; i++) {
        *(uint4*)(buf + ar[i] * SA + akq[i] * 4) = cvt4(pa[i]);
        *(uint4*)(buf + BG_OFF + bkk[i] * SBA + bnq[i] * 4) = cvt4(pg[i]);
        *(uint4*)(buf + BU_OFF + bkk[i] * SBA + bnq[i] * 4) = cvt4(pu[i]);
    }
    __syncthreads();

    const int NCH = H_DIM / 16;  // 64
    for (int c = 0; c < NCH; c++) {
        int k0n = (c + 1) * 16;
        if (c + 1 < NCH) {
#pragma unroll
            for (int i = 0; i < 2; i++) {
                int tok = toks_s[ar[i]];
                pa[i] = (tok >= 0) ? *(const float4*)(x + (size_t)tok * H_DIM + k0n + akq[i] * 4) : z4;
                pg[i] = *(const float4*)(Wg + (size_t)(k0n + bkk[i]) * F_DIM + bnq[i] * 4);
                pu[i] = *(const float4*)(Wu + (size_t)(k0n + bkk[i]) * F_DIM + bnq[i] * 4);
            }
        }
        const uint32_t* As = buf + (c & 1) * STG_A;
        const uint32_t* Bg = As + BG_OFF;
        const uint32_t* Bu = As + BU_OFF;
#pragma unroll
        for (int ks = 0; ks < 16; ks += 8) {
            uint32_t af[4][4];
#pragma unroll
            for (int mt = 0; mt < 4; mt++) {
                int m = mbase + mt * 16 + gid;
                af[mt][0] = As[m * SA + ks + tig];
                af[mt][1] = As[(m + 8) * SA + ks + tig];
                af[mt][2] = As[m * SA + ks + tig + 4];
                af[mt][3] = As[(m + 8) * SA + ks + tig + 4];
            }
#pragma unroll
            for (int nt = 0; nt < 4; nt++) {
                int n = nbase + nt * 8 + gid;
                uint32_t bg[2], bu[2];
                bg[0] = Bg[(ks + tig) * SBA + n];
                bg[1] = Bg[(ks + tig + 4) * SBA + n];
                bu[0] = Bu[(ks + tig) * SBA + n];
                bu[1] = Bu[(ks + tig + 4) * SBA + n];
#pragma unroll
                for (int mt = 0; mt < 4; mt++) mma_tf32(accG[mt][nt], af[mt], bg);
#pragma unroll
                for (int mt = 0; mt < 4; mt++) mma_tf32(accU[mt][nt], af[mt], bu);
            }
        }
        if (c + 1 < NCH) {
            uint32_t* Asn = buf + ((c + 1) & 1) * STG_A;
#pragma unroll
            for (int i = 0; i < 2; i++) {
                *(uint4*)(Asn + ar[i] * SA + akq[i] * 4) = cvt4(pa[i]);
                *(uint4*)(Asn + BG_OFF + bkk[i] * SBA + bnq[i] * 4) = cvt4(pg[i]);
                *(uint4*)(Asn + BU_OFF + bkk[i] * SBA + bnq[i] * 4) = cvt4(pu[i]);
            }
        }
        __syncthreads();
    }

    // epilogue: silu(gate)*up -> g_h
#pragma unroll
    for (int mt = 0; mt < 4; mt++) {
        int rl0 = mbase + mt * 16 + gid;
#pragma unroll
        for (int half = 0; half < 2; half++) {
            int r = m0 + rl0 + half * 8;
            if (r < cnt) {
                float* hp = g_h + (size_t)(base + r) * F_DIM + n0 + nbase;
#pragma unroll
                for (int nt = 0; nt < 4; nt++) {
                    float2 o;
                    o.x = silu_mul(accG[mt][nt][half * 2 + 0], accU[mt][nt][half * 2 + 0]);
                    o.y = silu_mul(accG[mt][nt][half * 2 + 1], accU[mt][nt][half * 2 + 1]);
                    *(float2*)(hp + nt * 8 + tig * 2) = o;
                }
            }
        }
    }
}

// ================= pass B: out += w * (H1 Wd), tf32 mma.sync ================
// CTA tile 128(M) x 256(N), BK=16; warps: wm = wid&1 (2x64), wn = wid>>1 (4x64)
#define SBB 264
#define B_OFF_B A_WORDS                      // 2560
#define STG_B  (A_WORDS + 16 * SBB)          // 6784 words
#define SMEM_B_BYTES (2 * STG_B * 4)

__global__ void __launch_bounds__(256, 1)
gemmB_kernel(const float* __restrict__ wd, float* __restrict__ out) {
    int e = blockIdx.z;
    int cnt = g_count[e];
    int m0 = blockIdx.y * 128;
    if (m0 >= cnt) return;
    int base = g_off[e];
    int n0 = blockIdx.x * 256;

    extern __shared__ __align__(16) char smem_raw[];
    uint32_t* buf = (uint32_t*)smem_raw;

    int tid = threadIdx.x, wid = tid >> 5, lane = tid & 31;
    int gid = lane >> 2, tig = lane & 3;
    int mbase = (wid & 1) * 64;
    int nbase = (wid >> 1) * 64;

    const float* Wd = wd + (size_t)e * F_DIM * H_DIM + n0;

    float acc[4][8][4];
#pragma unroll
    for (int mt = 0; mt < 4; mt++)
#pragma unroll
        for (int nt = 0; nt < 8; nt++)
#pragma unroll
            for (int i = 0; i < 4; i++) acc[mt][nt][i] = 0.f;

    int ar[2], akq[2], bkk[4], bnq[4];
#pragma unroll
    for (int i = 0; i < 2; i++) { int idx = tid + i * 256; ar[i] = idx >> 2; akq[i] = idx & 3; }
#pragma unroll
    for (int i = 0; i < 4; i++) { int idx = tid + i * 256; bkk[i] = idx >> 6; bnq[i] = idx & 63; }

    // A row slots (clamped; rows >= cnt discarded in epilogue)
    size_t arow[2];
#pragma unroll
    for (int i = 0; i < 2; i++) {
        int sl = base + m0 + ar[i];
        if (sl > N_SLOTS - 1) sl = N_SLOTS - 1;
        arow[i] = (size_t)sl * F_DIM;
    }

    float4 pa[2], pb[4];
#pragma unroll
    for (int i = 0; i < 2; i++) pa[i] = *(const float4*)(g_h + arow[i] + akq[i] * 4);
#pragma unroll
    for (int i = 0; i < 4; i++) pb[i] = *(const float4*)(Wd + (size_t)bkk[i] * H_DIM + bnq[i] * 4);
#pragma unroll
    for (int i = 0; i < 2; i++) *(uint4*)(buf + ar[i] * SA + akq[i] * 4) = cvt4(pa[i]);
#pragma unroll
    for (int i = 0; i < 4; i++) *(uint4*)(buf + B_OFF_B + bkk[i] * SBB + bnq[i] * 4) = cvt4(pb[i]);
    __syncthreads();

    const int NCH = F_DIM / 16;  // 256
    for (int c = 0; c < NCH; c++) {
        int k0n = (c + 1) * 16;
        if (c + 1 < NCH) {
#pragma unroll
            for (int i = 0; i < 2; i++) pa[i] = *(const float4*)(g_h + arow[i] + k0n + akq[i] * 4);
#pragma unroll
            for (int i = 0; i < 4; i++) pb[i] = *(const float4*)(Wd + (size_t)(k0n + bkk[i]) * H_DIM + bnq[i] * 4);
        }
        const uint32_t* As = buf + (c & 1) * STG_B;
        const uint32_t* Bs = As + B_OFF_B;
#pragma unroll
        for (int ks = 0; ks < 16; ks += 8) {
            uint32_t af[4][4];
#pragma unroll
            for (int mt = 0; mt < 4; mt++) {
                int m = mbase + mt * 16 + gid;
                af[mt][0] = As[m * SA + ks + tig];
                af[mt][1] = As[(m + 8) * SA + ks + tig];
                af[mt][2] = As[m * SA + ks + tig + 4];
                af[mt][3] = As[(m + 8) * SA + ks + tig + 4];
            }
#pragma unroll
            for (int nt = 0; nt < 8; nt++) {
                int n = nbase + nt * 8 + gid;
                uint32_t bf[2];
                bf[0] = Bs[(ks + tig) * SBB + n];
                bf[1] = Bs[(ks + tig + 4) * SBB + n];
#pragma unroll
                for (int mt = 0; mt < 4; mt++) mma_tf32(acc[mt][nt], af[mt], bf);
            }
        }
        if (c + 1 < NCH) {
            uint32_t* Asn = buf + ((c + 1) & 1) * STG_B;
#pragma unroll
            for (int i = 0; i < 2; i++) *(uint4*)(Asn + ar[i] * SA + akq[i] * 4) = cvt4(pa[i]);
#pragma unroll
            for (int i = 0; i < 4; i++) *(uint4*)(Asn + B_OFF_B + bkk[i] * SBB + bnq[i] * 4) = cvt4(pb[i]);
        }
        __syncthreads();
    }

    // epilogue: weighted atomic combine
    int tokr[8]; float wr[8];
#pragma unroll
    for (int mt = 0; mt < 4; mt++)
#pragma unroll
        for (int half = 0; half < 2; half++) {
            int r = m0 + mbase + mt * 16 + gid + half * 8;
            int li = mt * 2 + half;
            if (r < cnt) { tokr[li] = g_slot_tok[base + r]; wr[li] = g_slot_w[base + r]; }
            else tokr[li] = -1;
        }
#pragma unroll
    for (int mt = 0; mt < 4; mt++)
#pragma unroll
        for (int half = 0; half < 2; half++) {
            int li = mt * 2 + half;
            if (tokr[li] >= 0) {
                float* op = out + (size_t)tokr[li] * H_DIM + n0 + nbase + tig * 2;
                float w = wr[li];
#pragma unroll
                for (int nt = 0; nt < 8; nt++) {
                    atomicAdd(op + nt * 8 + 0, w * acc[mt][nt][half * 2 + 0]);
                    atomicAdd(op + nt * 8 + 1, w * acc[mt][nt][half * 2 + 1]);
                }
            }
        }
}

// ---------------- launch ----------------
extern "C" void kernel_launch(void* const* d_in, const int* in_sizes, int n_in,
                              void* d_out, int out_size) {
    const float* x  = (const float*)d_in[0];
    const float* gw = (const float*)d_in[1];
    const float* wg = (const float*)d_in[2];
    const float* wu = (const float*)d_in[3];
    const float* wd = (const float*)d_in[4];
    float* out = (float*)d_out;

    cudaFuncSetAttribute(gemmA_kernel, cudaFuncAttributeMaxDynamicSharedMemorySize, SMEM_A_BYTES);
    cudaFuncSetAttribute(gemmB_kernel, cudaFuncAttributeMaxDynamicSharedMemorySize, SMEM_B_BYTES);

    init_kernel<<<512, 256>>>(out, out_size);
    router_kernel<<<T_TOK / 8, 256>>>(x, gw);
    offsets_kernel<<<1, 1>>>();
    scatter_kernel<<<T_TOK / 256, 256>>>();
    reduce_kernel<<<1, 256>>>(out, out_size);

    // pass A: x = Nblk (fast, shares A rows in L2), y = Mblk, z = expert
    dim3 gA(F_DIM / 128, N_SLOTS / 128, E_NUM);
    gemmA_kernel<<<gA, 256, SMEM_A_BYTES>>>(x, wg, wu);

    dim3 gB(H_DIM / 256, N_SLOTS / 128, E_NUM);
    gemmB_kernel<<<gB, 256, SMEM_B_BYTES>>>(wd, out);
}

// round 4
// speedup vs baseline: 7.5606x; 1.8054x over previous
#include <cuda_runtime.h>
#include <cuda_fp16.h>
#include <math.h>
#include <stdint.h>

#define T_TOK 8192
#define H_DIM 1024
#define F_DIM 4096
#define E_NUM 8
#define N_SLOTS (T_TOK * 2)

// ---------------- scratch (device globals; no runtime allocation) ----------------
__device__ float g_probs[T_TOK * E_NUM];
__device__ float g_lse2[T_TOK];
__device__ int   g_tok_e[T_TOK * 2];
__device__ float g_tok_w[T_TOK * 2];
__device__ int   g_count[E_NUM];
__device__ int   g_off[E_NUM + 1];
__device__ int   g_cursor[E_NUM];
__device__ int   g_slot_tok[N_SLOTS];
__device__ float g_slot_w[N_SLOTS];

__device__ __half g_x16[(size_t)T_TOK * H_DIM];
__device__ __half g_wg16[(size_t)E_NUM * H_DIM * F_DIM];
__device__ __half g_wu16[(size_t)E_NUM * H_DIM * F_DIM];
__device__ __half g_wd16[(size_t)E_NUM * F_DIM * H_DIM];
__device__ __half g_h16[(size_t)N_SLOTS * F_DIM];   // 128 MB fp16 intermediate

// ---------------- PTX helpers ----------------
__device__ __forceinline__ uint32_t smem_u32(const void* p) {
    uint32_t a;
    asm("{ .reg .u64 t; cvta.to.shared.u64 t, %1; cvt.u32.u64 %0, t; }" : "=r"(a) : "l"(p));
    return a;
}
__device__ __forceinline__ void cp16(uint32_t dst, const void* src, uint32_t sz) {
    asm volatile("cp.async.cg.shared.global [%0], [%1], 16, %2;"
                 :: "r"(dst), "l"(__cvta_generic_to_global(src)), "r"(sz) : "memory");
}
__device__ __forceinline__ void cp_commit() {
    asm volatile("cp.async.commit_group;" ::: "memory");
}
__device__ __forceinline__ void ldsm4(uint32_t* r, uint32_t a) {
    asm volatile("ldmatrix.sync.aligned.m8n8.x4.shared.b16 {%0,%1,%2,%3}, [%4];"
                 : "=r"(r[0]), "=r"(r[1]), "=r"(r[2]), "=r"(r[3]) : "r"(a));
}
__device__ __forceinline__ void ldsm4t(uint32_t* r, uint32_t a) {
    asm volatile("ldmatrix.sync.aligned.m8n8.x4.trans.shared.b16 {%0,%1,%2,%3}, [%4];"
                 : "=r"(r[0]), "=r"(r[1]), "=r"(r[2]), "=r"(r[3]) : "r"(a));
}
__device__ __forceinline__ void mma_f16(float* c, const uint32_t* a, const uint32_t* b) {
    asm volatile("mma.sync.aligned.m16n8k16.row.col.f32.f16.f16.f32 "
                 "{%0,%1,%2,%3}, {%4,%5,%6,%7}, {%8,%9}, {%0,%1,%2,%3};"
                 : "+f"(c[0]), "+f"(c[1]), "+f"(c[2]), "+f"(c[3])
                 : "r"(a[0]), "r"(a[1]), "r"(a[2]), "r"(a[3]), "r"(b[0]), "r"(b[1]));
}
__device__ __forceinline__ float silu_mul(float g, float u) {
    return g / (1.f + __expf(-g)) * u;
}

// ---------------- init ----------------
__global__ void init_kernel(float* out, int n) {
    int tid = blockIdx.x * blockDim.x + threadIdx.x;
    if (tid < E_NUM) { g_count[tid] = 0; g_cursor[tid] = 0; }
    for (int i = tid; i < n; i += gridDim.x * blockDim.x) out[i] = 0.f;
}

// ---------------- fp32 -> fp16 conversion ----------------
__global__ void conv_kernel(const float* __restrict__ s, __half* __restrict__ d, int n) {
    int i = (blockIdx.x * 256 + threadIdx.x) * 4;
    if (i >= n) return;
    float4 v = *(const float4*)(s + i);
    union { __half2 h[2]; uint2 u; } pk;
    pk.h[0] = __floats2half2_rn(v.x, v.y);
    pk.h[1] = __floats2half2_rn(v.z, v.w);
    *(uint2*)(d + i) = pk.u;
}

// ---------------- router: one warp per token ----------------
__global__ void router_kernel(const float* __restrict__ x, const float* __restrict__ gw) {
    __shared__ float sgw[H_DIM * E_NUM];
    for (int i = threadIdx.x; i < H_DIM * E_NUM; i += blockDim.x) sgw[i] = gw[i];
    __syncthreads();

    int warp = threadIdx.x >> 5;
    int lane = threadIdx.x & 31;
    int t = blockIdx.x * (blockDim.x >> 5) + warp;
    if (t >= T_TOK) return;

    const float* xr = x + (size_t)t * H_DIM;
    float acc[E_NUM];
#pragma unroll
    for (int e = 0; e < E_NUM; e++) acc[e] = 0.f;
    for (int h = lane; h < H_DIM; h += 32) {
        float xv = xr[h];
#pragma unroll
        for (int e = 0; e < E_NUM; e++) acc[e] += xv * sgw[h * E_NUM + e];
    }
#pragma unroll
    for (int off = 16; off; off >>= 1)
#pragma unroll
        for (int e = 0; e < E_NUM; e++) acc[e] += __shfl_xor_sync(0xffffffffu, acc[e], off);

    if (lane == 0) {
        float m = acc[0];
#pragma unroll
        for (int e = 1; e < E_NUM; e++) m = fmaxf(m, acc[e]);
        float p[E_NUM], s = 0.f;
#pragma unroll
        for (int e = 0; e < E_NUM; e++) { p[e] = expf(acc[e] - m); s += p[e]; }
        float lse = m + logf(s);
        g_lse2[t] = lse * lse;
        float inv = 1.f / s;
#pragma unroll
        for (int e = 0; e < E_NUM; e++) { p[e] *= inv; g_probs[t * E_NUM + e] = p[e]; }
        int i1 = 0;
#pragma unroll
        for (int e = 1; e < E_NUM; e++) if (p[e] > p[i1]) i1 = e;
        int i2 = (i1 == 0) ? 1 : 0;
#pragma unroll
        for (int e = 0; e < E_NUM; e++) if (e != i1 && p[e] > p[i2]) i2 = e;
        float w1 = p[i1], w2 = p[i2];
        float ws = 1.f / (w1 + w2);
        g_tok_e[2 * t + 0] = i1;  g_tok_w[2 * t + 0] = w1 * ws;
        g_tok_e[2 * t + 1] = i2;  g_tok_w[2 * t + 1] = w2 * ws;
        atomicAdd(&g_count[i1], 1);
        atomicAdd(&g_count[i2], 1);
    }
}

__global__ void offsets_kernel() {
    g_off[0] = 0;
    for (int e = 0; e < E_NUM; e++) g_off[e + 1] = g_off[e] + g_count[e];
}

__global__ void scatter_kernel() {
    int t = blockIdx.x * blockDim.x + threadIdx.x;
    if (t >= T_TOK) return;
#pragma unroll
    for (int k = 0; k < 2; k++) {
        int e = g_tok_e[2 * t + k];
        int pos = g_off[e] + atomicAdd(&g_cursor[e], 1);
        g_slot_tok[pos] = t;
        g_slot_w[pos] = g_tok_w[2 * t + k];
    }
}

__global__ void reduce_kernel(float* out, int out_size) {
    __shared__ float sp[256 * E_NUM];
    __shared__ float sl[256];
    int tid = threadIdx.x;
    float lp[E_NUM];
#pragma unroll
    for (int e = 0; e < E_NUM; e++) lp[e] = 0.f;
    float ll = 0.f;
    for (int t = tid; t < T_TOK; t += 256) {
#pragma unroll
        for (int e = 0; e < E_NUM; e++) lp[e] += g_probs[t * E_NUM + e];
        ll += g_lse2[t];
    }
#pragma unroll
    for (int e = 0; e < E_NUM; e++) sp[tid * E_NUM + e] = lp[e];
    sl[tid] = ll;
    __syncthreads();
    for (int s = 128; s; s >>= 1) {
        if (tid < s) {
#pragma unroll
            for (int e = 0; e < E_NUM; e++) sp[tid * E_NUM + e] += sp[(tid + s) * E_NUM + e];
            sl[tid] += sl[tid + s];
        }
        __syncthreads();
    }
    if (tid == 0) {
        float bal = 0.f;
        for (int e = 0; e < E_NUM; e++) {
            float frac = (float)g_count[e] / (float)(T_TOK * 2);
            float meanp = sp[e] / (float)T_TOK;
            bal += frac * meanp;
        }
        out[out_size - 2] = bal * (float)E_NUM;
        out[out_size - 1] = sl[0] / (float)T_TOK;
    }
}

// ================= pass A: h = silu(X Wg)*(X Wu), fp16 mma + cp.async ================
// CTA 128M x 128N(gate)+128N(up), BK=32, 3-stage cp.async pipeline, ldmatrix frags.
// SMEM strides (bytes): A rows 80 (32h + 8 pad), B rows 272 (128h + 8 pad).
#define STG_A 27648
#define SMEM_A_BYTES (512 + 3 * STG_A)
#define STG_B 27136
#define SMEM_B_BYTES (3 * STG_B)

__global__ void __launch_bounds__(256, 1)
gemmA_kernel(const float* dummy) {
    int e = blockIdx.z;
    int cnt = g_count[e];
    int m0 = blockIdx.y * 128;
    if (m0 >= cnt) return;
    int base = g_off[e];
    int n0 = blockIdx.x * 128;

    extern __shared__ __align__(16) char dsm[];
    int* toks = (int*)dsm;
    uint32_t sb = smem_u32(dsm);

    int tid = threadIdx.x, wid = tid >> 5, lane = tid & 31;
    int gid = lane >> 2, tig = lane & 3;
    int mb = (wid & 1) * 64;
    int nb = (wid >> 1) * 32;

    if (tid < 128) {
        int idx = m0 + tid;
        toks[tid] = (idx < cnt) ? g_slot_tok[base + idx] : -1;
    }
    __syncthreads();

    const __half* Wg = g_wg16 + (size_t)e * H_DIM * F_DIM + n0;
    const __half* Wu = g_wu16 + (size_t)e * H_DIM * F_DIM + n0;

    // staging index precompute
    int a_row[2], a_j[2], b_row[2], b_j[2];
#pragma unroll
    for (int i = 0; i < 2; i++) {
        int i2 = tid + i * 256;
        a_row[i] = i2 >> 2;  a_j[i] = i2 & 3;
        b_row[i] = i2 >> 4;  b_j[i] = i2 & 15;
    }

    const int NCH = H_DIM / 32;  // 32
#define ISSUE_A(c, s)                                                                  \
    {                                                                                  \
        int k0 = (c) * 32;                                                             \
        uint32_t stg = sb + 512 + (s) * STG_A;                                         \
        _Pragma("unroll")                                                              \
        for (int i = 0; i < 2; i++) {                                                  \
            int tok = toks[a_row[i]];                                                  \
            const __half* src = g_x16 + (size_t)(tok < 0 ? 0 : tok) * H_DIM + k0 + a_j[i] * 8; \
            cp16(stg + a_row[i] * 80 + a_j[i] * 16, src, tok >= 0 ? 16u : 0u);         \
        }                                                                              \
        _Pragma("unroll")                                                              \
        for (int i = 0; i < 2; i++) {                                                  \
            cp16(stg + 10240 + b_row[i] * 272 + b_j[i] * 16,                           \
                 Wg + (size_t)(k0 + b_row[i]) * F_DIM + b_j[i] * 8, 16u);              \
            cp16(stg + 18944 + b_row[i] * 272 + b_j[i] * 16,                           \
                 Wu + (size_t)(k0 + b_row[i]) * F_DIM + b_j[i] * 8, 16u);              \
        }                                                                              \
        cp_commit();                                                                   \
    }

    ISSUE_A(0, 0);
    ISSUE_A(1, 1);

    float accG[4][4][4], accU[4][4][4];
#pragma unroll
    for (int mt = 0; mt < 4; mt++)
#pragma unroll
        for (int nt = 0; nt < 4; nt++)
#pragma unroll
            for (int i = 0; i < 4; i++) { accG[mt][nt][i] = 0.f; accU[mt][nt][i] = 0.f; }

    // fragment base addresses within a stage
    uint32_t aOff = (uint32_t)((mb + (lane & 15)) * 80 + (lane >> 4) * 16);
    uint32_t bOff = (uint32_t)((lane & 15) * 272 + (lane >> 4) * 16);

    for (int c = 0; c < NCH; c++) {
        if (c + 1 < NCH) asm volatile("cp.async.wait_group 1;" ::: "memory");
        else             asm volatile("cp.async.wait_group 0;" ::: "memory");
        __syncthreads();
        uint32_t stg = sb + 512 + (c % 3) * STG_A;
#pragma unroll
        for (int ks = 0; ks < 2; ks++) {
            uint32_t af[4][4];
#pragma unroll
            for (int mt = 0; mt < 4; mt++)
                ldsm4(af[mt], stg + aOff + mt * 16 * 80 + ks * 32);
            uint32_t bg[2][4], bu[2][4];
#pragma unroll
            for (int pr = 0; pr < 2; pr++) {
                uint32_t co = (uint32_t)((nb + pr * 16) * 2 + ks * 16 * 272);
                ldsm4t(bg[pr], stg + 10240 + bOff + co);
                ldsm4t(bu[pr], stg + 18944 + bOff + co);
            }
#pragma unroll
            for (int pr = 0; pr < 2; pr++)
#pragma unroll
                for (int hn = 0; hn < 2; hn++) {
                    int nt = pr * 2 + hn;
#pragma unroll
                    for (int mt = 0; mt < 4; mt++) {
                        mma_f16(accG[mt][nt], af[mt], bg[pr] + hn * 2);
                        mma_f16(accU[mt][nt], af[mt], bu[pr] + hn * 2);
                    }
                }
        }
        __syncthreads();
        if (c + 2 < NCH) ISSUE_A(c + 2, (c + 2) % 3);
    }

    // epilogue: silu(gate)*up -> g_h16
#pragma unroll
    for (int mt = 0; mt < 4; mt++)
#pragma unroll
        for (int half = 0; half < 2; half++) {
            int r = m0 + mb + mt * 16 + gid + half * 8;
            if (r < cnt) {
                __half* hp = g_h16 + (size_t)(base + r) * F_DIM + n0 + nb + tig * 2;
#pragma unroll
                for (int nt = 0; nt < 4; nt++) {
                    float h0 = silu_mul(accG[mt][nt][half * 2 + 0], accU[mt][nt][half * 2 + 0]);
                    float h1 = silu_mul(accG[mt][nt][half * 2 + 1], accU[mt][nt][half * 2 + 1]);
                    *(__half2*)(hp + nt * 8) = __floats2half2_rn(h0, h1);
                }
            }
        }
#undef ISSUE_A
}

// ================= pass B: out += w * (H1 Wd), fp16 mma + cp.async ================
// CTA 128M x 256N, BK=32; B rows 528B stride (256h + 8 pad).
__global__ void __launch_bounds__(256, 1)
gemmB_kernel(float* __restrict__ out) {
    int e = blockIdx.z;
    int cnt = g_count[e];
    int m0 = blockIdx.y * 128;
    if (m0 >= cnt) return;
    int base = g_off[e];
    int n0 = blockIdx.x * 256;

    extern __shared__ __align__(16) char dsm[];
    uint32_t sb = smem_u32(dsm);

    int tid = threadIdx.x, wid = tid >> 5, lane = tid & 31;
    int gid = lane >> 2, tig = lane & 3;
    int mb = (wid & 1) * 64;
    int nb = (wid >> 1) * 64;

    const __half* Wd = g_wd16 + (size_t)e * F_DIM * H_DIM + n0;

    int a_row[2], a_j[2], b_row[4], b_j[4];
#pragma unroll
    for (int i = 0; i < 2; i++) { int i2 = tid + i * 256; a_row[i] = i2 >> 2; a_j[i] = i2 & 3; }
#pragma unroll
    for (int i = 0; i < 4; i++) { int i2 = tid + i * 256; b_row[i] = i2 >> 5; b_j[i] = i2 & 31; }

    const int NCH = F_DIM / 32;  // 128
#define ISSUE_B(c, s)                                                                  \
    {                                                                                  \
        int k0 = (c) * 32;                                                             \
        uint32_t stg = sb + (s) * STG_B;                                               \
        _Pragma("unroll")                                                              \
        for (int i = 0; i < 2; i++) {                                                  \
            int r = m0 + a_row[i];                                                     \
            int ok = (r < cnt);                                                        \
            const __half* src = g_h16 + (size_t)(base + (ok ? r : 0)) * F_DIM + k0 + a_j[i] * 8; \
            cp16(stg + a_row[i] * 80 + a_j[i] * 16, src, ok ? 16u : 0u);               \
        }                                                                              \
        _Pragma("unroll")                                                              \
        for (int i = 0; i < 4; i++) {                                                  \
            cp16(stg + 10240 + b_row[i] * 528 + b_j[i] * 16,                           \
                 Wd + (size_t)(k0 + b_row[i]) * H_DIM + b_j[i] * 8, 16u);              \
        }                                                                              \
        cp_commit();                                                                   \
    }

    ISSUE_B(0, 0);
    ISSUE_B(1, 1);

    float acc[4][8][4];
#pragma unroll
    for (int mt = 0; mt < 4; mt++)
#pragma unroll
        for (int nt = 0; nt < 8; nt++)
#pragma unroll
            for (int i = 0; i < 4; i++) acc[mt][nt][i] = 0.f;

    uint32_t aOff = (uint32_t)((mb + (lane & 15)) * 80 + (lane >> 4) * 16);
    uint32_t bOff = (uint32_t)((lane & 15) * 528 + (lane >> 4) * 16);

    for (int c = 0; c < NCH; c++) {
        if (c + 1 < NCH) asm volatile("cp.async.wait_group 1;" ::: "memory");
        else             asm volatile("cp.async.wait_group 0;" ::: "memory");
        __syncthreads();
        uint32_t stg = sb + (c % 3) * STG_B;
#pragma unroll
        for (int ks = 0; ks < 2; ks++) {
            uint32_t af[4][4];
#pragma unroll
            for (int mt = 0; mt < 4; mt++)
                ldsm4(af[mt], stg + aOff + mt * 16 * 80 + ks * 32);
            uint32_t bf[4][4];
#pragma unroll
            for (int pr = 0; pr < 4; pr++) {
                uint32_t co = (uint32_t)((nb + pr * 16) * 2 + ks * 16 * 528);
                ldsm4t(bf[pr], stg + 10240 + bOff + co);
            }
#pragma unroll
            for (int pr = 0; pr < 4; pr++)
#pragma unroll
                for (int hn = 0; hn < 2; hn++) {
                    int nt = pr * 2 + hn;
#pragma unroll
                    for (int mt = 0; mt < 4; mt++)
                        mma_f16(acc[mt][nt], af[mt], bf[pr] + hn * 2);
                }
        }
        __syncthreads();
        if (c + 2 < NCH) ISSUE_B(c + 2, (c + 2) % 3);
    }

    // epilogue: weighted atomic combine
#pragma unroll
    for (int mt = 0; mt < 4; mt++)
#pragma unroll
        for (int half = 0; half < 2; half++) {
            int r = m0 + mb + mt * 16 + gid + half * 8;
            if (r < cnt) {
                int tok = g_slot_tok[base + r];
                float w = g_slot_w[base + r];
                float* op = out + (size_t)tok * H_DIM + n0 + nb + tig * 2;
#pragma unroll
                for (int nt = 0; nt < 8; nt++) {
                    atomicAdd(op + nt * 8 + 0, w * acc[mt][nt][half * 2 + 0]);
                    atomicAdd(op + nt * 8 + 1, w * acc[mt][nt][half * 2 + 1]);
                }
            }
        }
#undef ISSUE_B
}

// ---------------- launch ----------------
extern "C" void kernel_launch(void* const* d_in, const int* in_sizes, int n_in,
                              void* d_out, int out_size) {
    const float* x  = (const float*)d_in[0];
    const float* gw = (const float*)d_in[1];
    const float* wg = (const float*)d_in[2];
    const float* wu = (const float*)d_in[3];
    const float* wd = (const float*)d_in[4];
    float* out = (float*)d_out;

    cudaFuncSetAttribute(gemmA_kernel, cudaFuncAttributeMaxDynamicSharedMemorySize, SMEM_A_BYTES);
    cudaFuncSetAttribute(gemmB_kernel, cudaFuncAttributeMaxDynamicSharedMemorySize, SMEM_B_BYTES);

    init_kernel<<<512, 256>>>(out, out_size);

    __half* dx; __half* dg; __half* du; __half* dd;
    cudaGetSymbolAddress((void**)&dx, g_x16);
    cudaGetSymbolAddress((void**)&dg, g_wg16);
    cudaGetSymbolAddress((void**)&du, g_wu16);
    cudaGetSymbolAddress((void**)&dd, g_wd16);
    const int NW = E_NUM * H_DIM * F_DIM;
    conv_kernel<<<(T_TOK * H_DIM) / 1024, 256>>>(x, dx, T_TOK * H_DIM);
    conv_kernel<<<NW / 1024, 256>>>(wg, dg, NW);
    conv_kernel<<<NW / 1024, 256>>>(wu, du, NW);
    conv_kernel<<<NW / 1024, 256>>>(wd, dd, NW);

    router_kernel<<<T_TOK / 8, 256>>>(x, gw);
    offsets_kernel<<<1, 1>>>();
    scatter_kernel<<<T_TOK / 256, 256>>>();
    reduce_kernel<<<1, 256>>>(out, out_size);

    dim3 gA(F_DIM / 128, N_SLOTS / 128, E_NUM);
    gemmA_kernel<<<gA, 256, SMEM_A_BYTES>>>(x);

    dim3 gB(H_DIM / 256, N_SLOTS / 128, E_NUM);
    gemmB_kernel<<<gB, 256, SMEM_B_BYTES>>>(out);
}

// round 5
// speedup vs baseline: 7.7330x; 1.0228x over previous
#include <cuda_runtime.h>
#include <cuda_fp16.h>
#include <math.h>
#include <stdint.h>

#define T_TOK 8192
#define H_DIM 1024
#define F_DIM 4096
#define E_NUM 8
#define N_SLOTS (T_TOK * 2)

// ---------------- scratch (device globals; no runtime allocation) ----------------
__device__ float g_probs[T_TOK * E_NUM];
__device__ float g_lse2[T_TOK];
__device__ int   g_tok_e[T_TOK * 2];
__device__ float g_tok_w[T_TOK * 2];
__device__ int   g_count[E_NUM];
__device__ int   g_off[E_NUM + 1];
__device__ int   g_cursor[E_NUM];
__device__ int   g_slot_tok[N_SLOTS];
__device__ float g_slot_w[N_SLOTS];

__device__ __half g_x16[(size_t)T_TOK * H_DIM];
__device__ __half g_wg16[(size_t)E_NUM * H_DIM * F_DIM];
__device__ __half g_wu16[(size_t)E_NUM * H_DIM * F_DIM];
__device__ __half g_wd16[(size_t)E_NUM * F_DIM * H_DIM];
__device__ __half g_h16[(size_t)N_SLOTS * F_DIM];   // 128 MB fp16 intermediate

// ---------------- PTX helpers ----------------
__device__ __forceinline__ uint32_t smem_u32(const void* p) {
    uint32_t a;
    asm("{ .reg .u64 t; cvta.to.shared.u64 t, %1; cvt.u32.u64 %0, t; }" : "=r"(a) : "l"(p));
    return a;
}
__device__ __forceinline__ void cp16(uint32_t dst, const void* src, uint32_t sz) {
    asm volatile("cp.async.cg.shared.global [%0], [%1], 16, %2;"
                 :: "r"(dst), "l"(__cvta_generic_to_global(src)), "r"(sz) : "memory");
}
__device__ __forceinline__ void cp_commit() {
    asm volatile("cp.async.commit_group;" ::: "memory");
}
__device__ __forceinline__ void ldsm4(uint32_t* r, uint32_t a) {
    asm volatile("ldmatrix.sync.aligned.m8n8.x4.shared.b16 {%0,%1,%2,%3}, [%4];"
                 : "=r"(r[0]), "=r"(r[1]), "=r"(r[2]), "=r"(r[3]) : "r"(a));
}
__device__ __forceinline__ void ldsm4t(uint32_t* r, uint32_t a) {
    asm volatile("ldmatrix.sync.aligned.m8n8.x4.trans.shared.b16 {%0,%1,%2,%3}, [%4];"
                 : "=r"(r[0]), "=r"(r[1]), "=r"(r[2]), "=r"(r[3]) : "r"(a));
}
__device__ __forceinline__ void mma_f16(float* c, const uint32_t* a, const uint32_t* b) {
    asm volatile("mma.sync.aligned.m16n8k16.row.col.f32.f16.f16.f32 "
                 "{%0,%1,%2,%3}, {%4,%5,%6,%7}, {%8,%9}, {%0,%1,%2,%3};"
                 : "+f"(c[0]), "+f"(c[1]), "+f"(c[2]), "+f"(c[3])
                 : "r"(a[0]), "r"(a[1]), "r"(a[2]), "r"(a[3]), "r"(b[0]), "r"(b[1]));
}
__device__ __forceinline__ float silu_mul(float g, float u) {
    return g / (1.f + __expf(-g)) * u;
}

// ---------------- init ----------------
__global__ void init_kernel(float* out, int n) {
    int tid = blockIdx.x * blockDim.x + threadIdx.x;
    if (tid < E_NUM) { g_count[tid] = 0; g_cursor[tid] = 0; }
    for (int i = tid; i < n; i += gridDim.x * blockDim.x) out[i] = 0.f;
}

// ---------------- fp32 -> fp16 conversion (weights) ----------------
__global__ void conv_kernel(const float* __restrict__ s, __half* __restrict__ d, int n) {
    int i = (blockIdx.x * 256 + threadIdx.x) * 4;
    if (i >= n) return;
    float4 v = *(const float4*)(s + i);
    union { __half2 h[2]; uint2 u; } pk;
    pk.h[0] = __floats2half2_rn(v.x, v.y);
    pk.h[1] = __floats2half2_rn(v.z, v.w);
    *(uint2*)(d + i) = pk.u;
}

// ---------------- router: one warp per token (also emits x as fp16) ----------------
__global__ void router_kernel(const float* __restrict__ x, const float* __restrict__ gw) {
    __shared__ float sgw[H_DIM * E_NUM];
    for (int i = threadIdx.x; i < H_DIM * E_NUM; i += blockDim.x) sgw[i] = gw[i];
    __syncthreads();

    int warp = threadIdx.x >> 5;
    int lane = threadIdx.x & 31;
    int t = blockIdx.x * (blockDim.x >> 5) + warp;
    if (t >= T_TOK) return;

    const float* xr = x + (size_t)t * H_DIM;
    float acc[E_NUM];
#pragma unroll
    for (int e = 0; e < E_NUM; e++) acc[e] = 0.f;
    for (int h = lane; h < H_DIM; h += 32) {
        float xv = xr[h];
#pragma unroll
        for (int e = 0; e < E_NUM; e++) acc[e] += xv * sgw[h * E_NUM + e];
    }

    // fp16 copy of this row (x row is hot in L1)
    {
        __half* dx = g_x16 + (size_t)t * H_DIM;
#pragma unroll
        for (int k = 0; k < H_DIM / 4 / 32; k++) {
            int idx = (lane + k * 32) * 4;
            float4 v = *(const float4*)(xr + idx);
            union { __half2 h[2]; uint2 u; } pk;
            pk.h[0] = __floats2half2_rn(v.x, v.y);
            pk.h[1] = __floats2half2_rn(v.z, v.w);
            *(uint2*)(dx + idx) = pk.u;
        }
    }

#pragma unroll
    for (int off = 16; off; off >>= 1)
#pragma unroll
        for (int e = 0; e < E_NUM; e++) acc[e] += __shfl_xor_sync(0xffffffffu, acc[e], off);

    if (lane == 0) {
        float m = acc[0];
#pragma unroll
        for (int e = 1; e < E_NUM; e++) m = fmaxf(m, acc[e]);
        float p[E_NUM], s = 0.f;
#pragma unroll
        for (int e = 0; e < E_NUM; e++) { p[e] = expf(acc[e] - m); s += p[e]; }
        float lse = m + logf(s);
        g_lse2[t] = lse * lse;
        float inv = 1.f / s;
#pragma unroll
        for (int e = 0; e < E_NUM; e++) { p[e] *= inv; g_probs[t * E_NUM + e] = p[e]; }
        int i1 = 0;
#pragma unroll
        for (int e = 1; e < E_NUM; e++) if (p[e] > p[i1]) i1 = e;
        int i2 = (i1 == 0) ? 1 : 0;
#pragma unroll
        for (int e = 0; e < E_NUM; e++) if (e != i1 && p[e] > p[i2]) i2 = e;
        float w1 = p[i1], w2 = p[i2];
        float ws = 1.f / (w1 + w2);
        g_tok_e[2 * t + 0] = i1;  g_tok_w[2 * t + 0] = w1 * ws;
        g_tok_e[2 * t + 1] = i2;  g_tok_w[2 * t + 1] = w2 * ws;
        atomicAdd(&g_count[i1], 1);
        atomicAdd(&g_count[i2], 1);
    }
}

__global__ void offsets_kernel() {
    g_off[0] = 0;
    for (int e = 0; e < E_NUM; e++) g_off[e + 1] = g_off[e] + g_count[e];
}

__global__ void scatter_kernel() {
    int t = blockIdx.x * blockDim.x + threadIdx.x;
    if (t >= T_TOK) return;
#pragma unroll
    for (int k = 0; k < 2; k++) {
        int e = g_tok_e[2 * t + k];
        int pos = g_off[e] + atomicAdd(&g_cursor[e], 1);
        g_slot_tok[pos] = t;
        g_slot_w[pos] = g_tok_w[2 * t + k];
    }
}

__global__ void reduce_kernel(float* out, int out_size) {
    __shared__ float sp[256 * E_NUM];
    __shared__ float sl[256];
    int tid = threadIdx.x;
    float lp[E_NUM];
#pragma unroll
    for (int e = 0; e < E_NUM; e++) lp[e] = 0.f;
    float ll = 0.f;
    for (int t = tid; t < T_TOK; t += 256) {
#pragma unroll
        for (int e = 0; e < E_NUM; e++) lp[e] += g_probs[t * E_NUM + e];
        ll += g_lse2[t];
    }
#pragma unroll
    for (int e = 0; e < E_NUM; e++) sp[tid * E_NUM + e] = lp[e];
    sl[tid] = ll;
    __syncthreads();
    for (int s = 128; s; s >>= 1) {
        if (tid < s) {
#pragma unroll
            for (int e = 0; e < E_NUM; e++) sp[tid * E_NUM + e] += sp[(tid + s) * E_NUM + e];
            sl[tid] += sl[tid + s];
        }
        __syncthreads();
    }
    if (tid == 0) {
        float bal = 0.f;
        for (int e = 0; e < E_NUM; e++) {
            float frac = (float)g_count[e] / (float)(T_TOK * 2);
            float meanp = sp[e] / (float)T_TOK;
            bal += frac * meanp;
        }
        out[out_size - 2] = bal * (float)E_NUM;
        out[out_size - 1] = sl[0] / (float)T_TOK;
    }
}

// ================= pass A: h = silu(X Wg)*(X Wu), fp16 mma + cp.async ================
// CTA 128M x 128N(gate)+128N(up), BK=32, 3-stage cp.async pipeline, 1 sync/iter.
// SMEM strides (bytes): A rows 80 (32h + 8 pad), B rows 272 (128h + 8 pad).
#define STG_A 27648
#define SMEM_A_BYTES (512 + 3 * STG_A)
#define STG_B 27136
#define SMEM_B_BYTES (3 * STG_B)

__global__ void __launch_bounds__(256, 1)
gemmA_kernel() {
    int e = blockIdx.z;
    int cnt = g_count[e];
    int m0 = blockIdx.y * 128;
    if (m0 >= cnt) return;
    int base = g_off[e];
    int n0 = blockIdx.x * 128;

    extern __shared__ __align__(16) char dsm[];
    int* toks = (int*)dsm;
    uint32_t sb = smem_u32(dsm);

    int tid = threadIdx.x, wid = tid >> 5, lane = tid & 31;
    int gid = lane >> 2, tig = lane & 3;
    int mb = (wid & 1) * 64;
    int nb = (wid >> 1) * 32;

    if (tid < 128) {
        int idx = m0 + tid;
        toks[tid] = (idx < cnt) ? g_slot_tok[base + idx] : -1;
    }
    __syncthreads();

    const __half* Wg = g_wg16 + (size_t)e * H_DIM * F_DIM + n0;
    const __half* Wu = g_wu16 + (size_t)e * H_DIM * F_DIM + n0;

    int a_row[2], a_j[2], b_row[2], b_j[2];
#pragma unroll
    for (int i = 0; i < 2; i++) {
        int i2 = tid + i * 256;
        a_row[i] = i2 >> 2;  a_j[i] = i2 & 3;
        b_row[i] = i2 >> 4;  b_j[i] = i2 & 15;
    }

    const int NCH = H_DIM / 32;  // 32
#define ISSUE_A(c, s)                                                                  \
    {                                                                                  \
        int k0 = (c) * 32;                                                             \
        uint32_t stg_i = sb + 512 + (s) * STG_A;                                       \
        _Pragma("unroll")                                                              \
        for (int i = 0; i < 2; i++) {                                                  \
            int tok = toks[a_row[i]];                                                  \
            const __half* src = g_x16 + (size_t)(tok < 0 ? 0 : tok) * H_DIM + k0 + a_j[i] * 8; \
            cp16(stg_i + a_row[i] * 80 + a_j[i] * 16, src, tok >= 0 ? 16u : 0u);       \
        }                                                                              \
        _Pragma("unroll")                                                              \
        for (int i = 0; i < 2; i++) {                                                  \
            cp16(stg_i + 10240 + b_row[i] * 272 + b_j[i] * 16,                         \
                 Wg + (size_t)(k0 + b_row[i]) * F_DIM + b_j[i] * 8, 16u);              \
            cp16(stg_i + 18944 + b_row[i] * 272 + b_j[i] * 16,                         \
                 Wu + (size_t)(k0 + b_row[i]) * F_DIM + b_j[i] * 8, 16u);              \
        }                                                                              \
        cp_commit();                                                                   \
    }

    ISSUE_A(0, 0);
    ISSUE_A(1, 1);

    float accG[4][4][4], accU[4][4][4];
#pragma unroll
    for (int mt = 0; mt < 4; mt++)
#pragma unroll
        for (int nt = 0; nt < 4; nt++)
#pragma unroll
            for (int i = 0; i < 4; i++) { accG[mt][nt][i] = 0.f; accU[mt][nt][i] = 0.f; }

    uint32_t aOff = (uint32_t)((mb + (lane & 15)) * 80 + (lane >> 4) * 16);
    uint32_t bOff = (uint32_t)((lane & 15) * 272 + (lane >> 4) * 16);

    for (int c = 0; c < NCH; c++) {
        if (c + 1 < NCH) asm volatile("cp.async.wait_group 1;" ::: "memory");
        else             asm volatile("cp.async.wait_group 0;" ::: "memory");
        __syncthreads();                 // all warps past iter c-1 compute; stage c ready
        if (c + 2 < NCH) ISSUE_A(c + 2, (c + 2) % 3);   // overlaps compute of stage c
        uint32_t stg = sb + 512 + (c % 3) * STG_A;
#pragma unroll
        for (int ks = 0; ks < 2; ks++) {
            uint32_t af[4][4];
#pragma unroll
            for (int mt = 0; mt < 4; mt++)
                ldsm4(af[mt], stg + aOff + mt * 16 * 80 + ks * 32);
            uint32_t bg[2][4], bu[2][4];
#pragma unroll
            for (int pr = 0; pr < 2; pr++) {
                uint32_t co = (uint32_t)((nb + pr * 16) * 2 + ks * 16 * 272);
                ldsm4t(bg[pr], stg + 10240 + bOff + co);
                ldsm4t(bu[pr], stg + 18944 + bOff + co);
            }
#pragma unroll
            for (int pr = 0; pr < 2; pr++)
#pragma unroll
                for (int hn = 0; hn < 2; hn++) {
                    int nt = pr * 2 + hn;
#pragma unroll
                    for (int mt = 0; mt < 4; mt++) {
                        mma_f16(accG[mt][nt], af[mt], bg[pr] + hn * 2);
                        mma_f16(accU[mt][nt], af[mt], bu[pr] + hn * 2);
                    }
                }
        }
    }

    // epilogue: silu(gate)*up -> g_h16
#pragma unroll
    for (int mt = 0; mt < 4; mt++)
#pragma unroll
        for (int half = 0; half < 2; half++) {
            int r = m0 + mb + mt * 16 + gid + half * 8;
            if (r < cnt) {
                __half* hp = g_h16 + (size_t)(base + r) * F_DIM + n0 + nb + tig * 2;
#pragma unroll
                for (int nt = 0; nt < 4; nt++) {
                    float h0 = silu_mul(accG[mt][nt][half * 2 + 0], accU[mt][nt][half * 2 + 0]);
                    float h1 = silu_mul(accG[mt][nt][half * 2 + 1], accU[mt][nt][half * 2 + 1]);
                    *(__half2*)(hp + nt * 8) = __floats2half2_rn(h0, h1);
                }
            }
        }
#undef ISSUE_A
}

// ================= pass B: out += w * (H1 Wd), fp16 mma + cp.async ================
// CTA 128M x 256N, BK=32; B rows 528B stride; 1 sync/iter.
__global__ void __launch_bounds__(256, 1)
gemmB_kernel(float* __restrict__ out) {
    int e = blockIdx.z;
    int cnt = g_count[e];
    int m0 = blockIdx.y * 128;
    if (m0 >= cnt) return;
    int base = g_off[e];
    int n0 = blockIdx.x * 256;

    extern __shared__ __align__(16) char dsm[];
    uint32_t sb = smem_u32(dsm);

    int tid = threadIdx.x, wid = tid >> 5, lane = tid & 31;
    int gid = lane >> 2, tig = lane & 3;
    int mb = (wid & 1) * 64;
    int nb = (wid >> 1) * 64;

    const __half* Wd = g_wd16 + (size_t)e * F_DIM * H_DIM + n0;

    int a_row[2], a_j[2], b_row[4], b_j[4];
#pragma unroll
    for (int i = 0; i < 2; i++) { int i2 = tid + i * 256; a_row[i] = i2 >> 2; a_j[i] = i2 & 3; }
#pragma unroll
    for (int i = 0; i < 4; i++) { int i2 = tid + i * 256; b_row[i] = i2 >> 5; b_j[i] = i2 & 31; }

    const int NCH = F_DIM / 32;  // 128
#define ISSUE_B(c, s)                                                                  \
    {                                                                                  \
        int k0 = (c) * 32;                                                             \
        uint32_t stg_i = sb + (s) * STG_B;                                             \
        _Pragma("unroll")                                                              \
        for (int i = 0; i < 2; i++) {                                                  \
            int r = m0 + a_row[i];                                                     \
            int ok = (r < cnt);                                                        \
            const __half* src = g_h16 + (size_t)(base + (ok ? r : 0)) * F_DIM + k0 + a_j[i] * 8; \
            cp16(stg_i + a_row[i] * 80 + a_j[i] * 16, src, ok ? 16u : 0u);             \
        }                                                                              \
        _Pragma("unroll")                                                              \
        for (int i = 0; i < 4; i++) {                                                  \
            cp16(stg_i + 10240 + b_row[i] * 528 + b_j[i] * 16,                         \
                 Wd + (size_t)(k0 + b_row[i]) * H_DIM + b_j[i] * 8, 16u);              \
        }                                                                              \
        cp_commit();                                                                   \
    }

    ISSUE_B(0, 0);
    ISSUE_B(1, 1);

    float acc[4][8][4];
#pragma unroll
    for (int mt = 0; mt < 4; mt++)
#pragma unroll
        for (int nt = 0; nt < 8; nt++)
#pragma unroll
            for (int i = 0; i < 4; i++) acc[mt][nt][i] = 0.f;

    uint32_t aOff = (uint32_t)((mb + (lane & 15)) * 80 + (lane >> 4) * 16);
    uint32_t bOff = (uint32_t)((lane & 15) * 528 + (lane >> 4) * 16);

    for (int c = 0; c < NCH; c++) {
        if (c + 1 < NCH) asm volatile("cp.async.wait_group 1;" ::: "memory");
        else             asm volatile("cp.async.wait_group 0;" ::: "memory");
        __syncthreads();
        if (c + 2 < NCH) ISSUE_B(c + 2, (c + 2) % 3);
        uint32_t stg = sb + (c % 3) * STG_B;
#pragma unroll
        for (int ks = 0; ks < 2; ks++) {
            uint32_t af[4][4];
#pragma unroll
            for (int mt = 0; mt < 4; mt++)
                ldsm4(af[mt], stg + aOff + mt * 16 * 80 + ks * 32);
            uint32_t bf[4][4];
#pragma unroll
            for (int pr = 0; pr < 4; pr++) {
                uint32_t co = (uint32_t)((nb + pr * 16) * 2 + ks * 16 * 528);
                ldsm4t(bf[pr], stg + 10240 + bOff + co);
            }
#pragma unroll
            for (int pr = 0; pr < 4; pr++)
#pragma unroll
                for (int hn = 0; hn < 2; hn++) {
                    int nt = pr * 2 + hn;
#pragma unroll
                    for (int mt = 0; mt < 4; mt++)
                        mma_f16(acc[mt][nt], af[mt], bf[pr] + hn * 2);
                }
        }
    }

    // epilogue: weighted atomic combine
#pragma unroll
    for (int mt = 0; mt < 4; mt++)
#pragma unroll
        for (int half = 0; half < 2; half++) {
            int r = m0 + mb + mt * 16 + gid + half * 8;
            if (r < cnt) {
                int tok = g_slot_tok[base + r];
                float w = g_slot_w[base + r];
                float* op = out + (size_t)tok * H_DIM + n0 + nb + tig * 2;
#pragma unroll
                for (int nt = 0; nt < 8; nt++) {
                    atomicAdd(op + nt * 8 + 0, w * acc[mt][nt][half * 2 + 0]);
                    atomicAdd(op + nt * 8 + 1, w * acc[mt][nt][half * 2 + 1]);
                }
            }
        }
#undef ISSUE_B
}

// ---------------- launch ----------------
extern "C" void kernel_launch(void* const* d_in, const int* in_sizes, int n_in,
                              void* d_out, int out_size) {
    const float* x  = (const float*)d_in[0];
    const float* gw = (const float*)d_in[1];
    const float* wg = (const float*)d_in[2];
    const float* wu = (const float*)d_in[3];
    const float* wd = (const float*)d_in[4];
    float* out = (float*)d_out;

    cudaFuncSetAttribute(gemmA_kernel, cudaFuncAttributeMaxDynamicSharedMemorySize, SMEM_A_BYTES);
    cudaFuncSetAttribute(gemmB_kernel, cudaFuncAttributeMaxDynamicSharedMemorySize, SMEM_B_BYTES);

    init_kernel<<<512, 256>>>(out, out_size);

    __half* dg; __half* du; __half* dd;
    cudaGetSymbolAddress((void**)&dg, g_wg16);
    cudaGetSymbolAddress((void**)&du, g_wu16);
    cudaGetSymbolAddress((void**)&dd, g_wd16);
    const int NW = E_NUM * H_DIM * F_DIM;
    conv_kernel<<<NW / 1024, 256>>>(wg, dg, NW);
    conv_kernel<<<NW / 1024, 256>>>(wu, du, NW);
    conv_kernel<<<NW / 1024, 256>>>(wd, dd, NW);

    router_kernel<<<T_TOK / 8, 256>>>(x, gw);   // also writes g_x16
    offsets_kernel<<<1, 1>>>();
    scatter_kernel<<<T_TOK / 256, 256>>>();
    reduce_kernel<<<1, 256>>>(out, out_size);

    dim3 gA(F_DIM / 128, N_SLOTS / 128, E_NUM);
    gemmA_kernel<<<gA, 256, SMEM_A_BYTES>>>();

    dim3 gB(H_DIM / 256, N_SLOTS / 128, E_NUM);
    gemmB_kernel<<<gB, 256, SMEM_B_BYTES>>>(out);
}

// round 6
// speedup vs baseline: 7.7338x; 1.0001x over previous
#include <cuda_runtime.h>
#include <cuda_fp16.h>
#include <math.h>
#include <stdint.h>

#define T_TOK 8192
#define H_DIM 1024
#define F_DIM 4096
#define E_NUM 8
#define N_SLOTS (T_TOK * 2)

// ---------------- scratch (device globals; no runtime allocation) ----------------
__device__ float g_probs[T_TOK * E_NUM];
__device__ float g_lse2[T_TOK];
__device__ int   g_tok_e[T_TOK * 2];
__device__ float g_tok_w[T_TOK * 2];
__device__ int   g_count[E_NUM];
__device__ int   g_off[E_NUM + 1];
__device__ int   g_cursor[E_NUM];
__device__ int   g_slot_tok[N_SLOTS];
__device__ float g_slot_w[N_SLOTS];

__device__ __half g_x16[(size_t)T_TOK * H_DIM];
__device__ __half g_wg16[(size_t)E_NUM * H_DIM * F_DIM];
__device__ __half g_wu16[(size_t)E_NUM * H_DIM * F_DIM];
__device__ __half g_wd16[(size_t)E_NUM * F_DIM * H_DIM];
__device__ __half g_h16[(size_t)N_SLOTS * F_DIM];   // 128 MB fp16 intermediate

// ---------------- PTX helpers ----------------
__device__ __forceinline__ uint32_t smem_u32(const void* p) {
    uint32_t a;
    asm("{ .reg .u64 t; cvta.to.shared.u64 t, %1; cvt.u32.u64 %0, t; }" : "=r"(a) : "l"(p));
    return a;
}
__device__ __forceinline__ void cp16(uint32_t dst, const void* src, uint32_t sz) {
    asm volatile("cp.async.cg.shared.global [%0], [%1], 16, %2;"
                 :: "r"(dst), "l"(__cvta_generic_to_global(src)), "r"(sz) : "memory");
}
__device__ __forceinline__ void cp_commit() {
    asm volatile("cp.async.commit_group;" ::: "memory");
}
__device__ __forceinline__ void ldsm4(uint32_t* r, uint32_t a) {
    asm volatile("ldmatrix.sync.aligned.m8n8.x4.shared.b16 {%0,%1,%2,%3}, [%4];"
                 : "=r"(r[0]), "=r"(r[1]), "=r"(r[2]), "=r"(r[3]) : "r"(a));
}
__device__ __forceinline__ void ldsm4t(uint32_t* r, uint32_t a) {
    asm volatile("ldmatrix.sync.aligned.m8n8.x4.trans.shared.b16 {%0,%1,%2,%3}, [%4];"
                 : "=r"(r[0]), "=r"(r[1]), "=r"(r[2]), "=r"(r[3]) : "r"(a));
}
__device__ __forceinline__ void mma_f16(float* c, const uint32_t* a, const uint32_t* b) {
    asm volatile("mma.sync.aligned.m16n8k16.row.col.f32.f16.f16.f32 "
                 "{%0,%1,%2,%3}, {%4,%5,%6,%7}, {%8,%9}, {%0,%1,%2,%3};"
                 : "+f"(c[0]), "+f"(c[1]), "+f"(c[2]), "+f"(c[3])
                 : "r"(a[0]), "r"(a[1]), "r"(a[2]), "r"(a[3]), "r"(b[0]), "r"(b[1]));
}
__device__ __forceinline__ float silu_mul(float g, float u) {
    return g / (1.f + __expf(-g)) * u;
}

// ---------------- init ----------------
__global__ void init_kernel(float* out, int n) {
    int tid = blockIdx.x * blockDim.x + threadIdx.x;
    if (tid < E_NUM) { g_count[tid] = 0; g_cursor[tid] = 0; }
    for (int i = tid; i < n; i += gridDim.x * blockDim.x) out[i] = 0.f;
}

// ---------------- fp32 -> fp16 conversion (weights) ----------------
__global__ void conv_kernel(const float* __restrict__ s, __half* __restrict__ d, int n) {
    int i = (blockIdx.x * 256 + threadIdx.x) * 4;
    if (i >= n) return;
    float4 v = *(const float4*)(s + i);
    union { __half2 h[2]; uint2 u; } pk;
    pk.h[0] = __floats2half2_rn(v.x, v.y);
    pk.h[1] = __floats2half2_rn(v.z, v.w);
    *(uint2*)(d + i) = pk.u;
}

// ---------------- router: one warp per token (also emits x as fp16) ----------------
__global__ void router_kernel(const float* __restrict__ x, const float* __restrict__ gw) {
    __shared__ float sgw[H_DIM * E_NUM];
    for (int i = threadIdx.x; i < H_DIM * E_NUM; i += blockDim.x) sgw[i] = gw[i];
    __syncthreads();

    int warp = threadIdx.x >> 5;
    int lane = threadIdx.x & 31;
    int t = blockIdx.x * (blockDim.x >> 5) + warp;
    if (t >= T_TOK) return;

    const float* xr = x + (size_t)t * H_DIM;
    float acc[E_NUM];
#pragma unroll
    for (int e = 0; e < E_NUM; e++) acc[e] = 0.f;
    for (int h = lane; h < H_DIM; h += 32) {
        float xv = xr[h];
#pragma unroll
        for (int e = 0; e < E_NUM; e++) acc[e] += xv * sgw[h * E_NUM + e];
    }

    // fp16 copy of this row (x row is hot in L1)
    {
        __half* dx = g_x16 + (size_t)t * H_DIM;
#pragma unroll
        for (int k = 0; k < H_DIM / 4 / 32; k++) {
            int idx = (lane + k * 32) * 4;
            float4 v = *(const float4*)(xr + idx);
            union { __half2 h[2]; uint2 u; } pk;
            pk.h[0] = __floats2half2_rn(v.x, v.y);
            pk.h[1] = __floats2half2_rn(v.z, v.w);
            *(uint2*)(dx + idx) = pk.u;
        }
    }

#pragma unroll
    for (int off = 16; off; off >>= 1)
#pragma unroll
        for (int e = 0; e < E_NUM; e++) acc[e] += __shfl_xor_sync(0xffffffffu, acc[e], off);

    if (lane == 0) {
        float m = acc[0];
#pragma unroll
        for (int e = 1; e < E_NUM; e++) m = fmaxf(m, acc[e]);
        float p[E_NUM], s = 0.f;
#pragma unroll
        for (int e = 0; e < E_NUM; e++) { p[e] = expf(acc[e] - m); s += p[e]; }
        float lse = m + logf(s);
        g_lse2[t] = lse * lse;
        float inv = 1.f / s;
#pragma unroll
        for (int e = 0; e < E_NUM; e++) { p[e] *= inv; g_probs[t * E_NUM + e] = p[e]; }
        int i1 = 0;
#pragma unroll
        for (int e = 1; e < E_NUM; e++) if (p[e] > p[i1]) i1 = e;
        int i2 = (i1 == 0) ? 1 : 0;
#pragma unroll
        for (int e = 0; e < E_NUM; e++) if (e != i1 && p[e] > p[i2]) i2 = e;
        float w1 = p[i1], w2 = p[i2];
        float ws = 1.f / (w1 + w2);
        g_tok_e[2 * t + 0] = i1;  g_tok_w[2 * t + 0] = w1 * ws;
        g_tok_e[2 * t + 1] = i2;  g_tok_w[2 * t + 1] = w2 * ws;
        atomicAdd(&g_count[i1], 1);
        atomicAdd(&g_count[i2], 1);
    }
}

__global__ void offsets_kernel() {
    g_off[0] = 0;
    for (int e = 0; e < E_NUM; e++) g_off[e + 1] = g_off[e] + g_count[e];
}

__global__ void scatter_kernel() {
    int t = blockIdx.x * blockDim.x + threadIdx.x;
    if (t >= T_TOK) return;
#pragma unroll
    for (int k = 0; k < 2; k++) {
        int e = g_tok_e[2 * t + k];
        int pos = g_off[e] + atomicAdd(&g_cursor[e], 1);
        g_slot_tok[pos] = t;
        g_slot_w[pos] = g_tok_w[2 * t + k];
    }
}

__global__ void reduce_kernel(float* out, int out_size) {
    __shared__ float sp[256 * E_NUM];
    __shared__ float sl[256];
    int tid = threadIdx.x;
    float lp[E_NUM];
#pragma unroll
    for (int e = 0; e < E_NUM; e++) lp[e] = 0.f;
    float ll = 0.f;
    for (int t = tid; t < T_TOK; t += 256) {
#pragma unroll
        for (int e = 0; e < E_NUM; e++) lp[e] += g_probs[t * E_NUM + e];
        ll += g_lse2[t];
    }
#pragma unroll
    for (int e = 0; e < E_NUM; e++) sp[tid * E_NUM + e] = lp[e];
    sl[tid] = ll;
    __syncthreads();
    for (int s = 128; s; s >>= 1) {
        if (tid < s) {
#pragma unroll
            for (int e = 0; e < E_NUM; e++) sp[tid * E_NUM + e] += sp[(tid + s) * E_NUM + e];
            sl[tid] += sl[tid + s];
        }
        __syncthreads();
    }
    if (tid == 0) {
        float bal = 0.f;
        for (int e = 0; e < E_NUM; e++) {
            float frac = (float)g_count[e] / (float)(T_TOK * 2);
            float meanp = sp[e] / (float)T_TOK;
            bal += frac * meanp;
        }
        out[out_size - 2] = bal * (float)E_NUM;
        out[out_size - 1] = sl[0] / (float)T_TOK;
    }
}

// ================= pass A: h = silu(X Wg)*(X Wu), fp16 mma + cp.async ================
// CTA 128M x 128N(gate)+128N(up), BK=32, 3-stage cp.async pipeline, 1 sync/iter.
// SMEM strides (bytes): A rows 80 (32h + 8 pad), B rows 272 (128h + 8 pad).
#define STG_A 27648
#define SMEM_A_BYTES (512 + 3 * STG_A)
#define STG_B 27136
#define SMEM_B_BYTES (3 * STG_B)

__global__ void __launch_bounds__(256, 1)
gemmA_kernel() {
    int e = blockIdx.z;
    int cnt = g_count[e];
    int m0 = blockIdx.y * 128;
    if (m0 >= cnt) return;
    int base = g_off[e];
    int n0 = blockIdx.x * 128;

    extern __shared__ __align__(16) char dsm[];
    int* toks = (int*)dsm;
    uint32_t sb = smem_u32(dsm);

    int tid = threadIdx.x, wid = tid >> 5, lane = tid & 31;
    int gid = lane >> 2, tig = lane & 3;
    int mb = (wid & 1) * 64;
    int nb = (wid >> 1) * 32;

    if (tid < 128) {
        int idx = m0 + tid;
        toks[tid] = (idx < cnt) ? g_slot_tok[base + idx] : -1;
    }
    __syncthreads();

    const __half* Wg = g_wg16 + (size_t)e * H_DIM * F_DIM + n0;
    const __half* Wu = g_wu16 + (size_t)e * H_DIM * F_DIM + n0;

    int a_row[2], a_j[2], b_row[2], b_j[2];
#pragma unroll
    for (int i = 0; i < 2; i++) {
        int i2 = tid + i * 256;
        a_row[i] = i2 >> 2;  a_j[i] = i2 & 3;
        b_row[i] = i2 >> 4;  b_j[i] = i2 & 15;
    }

    const int NCH = H_DIM / 32;  // 32
#define ISSUE_A(c, s)                                                                  \
    {                                                                                  \
        int k0 = (c) * 32;                                                             \
        uint32_t stg_i = sb + 512 + (s) * STG_A;                                       \
        _Pragma("unroll")                                                              \
        for (int i = 0; i < 2; i++) {                                                  \
            int tok = toks[a_row[i]];                                                  \
            const __half* src = g_x16 + (size_t)(tok < 0 ? 0 : tok) * H_DIM + k0 + a_j[i] * 8; \
            cp16(stg_i + a_row[i] * 80 + a_j[i] * 16, src, tok >= 0 ? 16u : 0u);       \
        }                                                                              \
        _Pragma("unroll")                                                              \
        for (int i = 0; i < 2; i++) {                                                  \
            cp16(stg_i + 10240 + b_row[i] * 272 + b_j[i] * 16,                         \
                 Wg + (size_t)(k0 + b_row[i]) * F_DIM + b_j[i] * 8, 16u);              \
            cp16(stg_i + 18944 + b_row[i] * 272 + b_j[i] * 16,                         \
                 Wu + (size_t)(k0 + b_row[i]) * F_DIM + b_j[i] * 8, 16u);              \
        }                                                                              \
        cp_commit();                                                                   \
    }

    ISSUE_A(0, 0);
    ISSUE_A(1, 1);

    float accG[4][4][4], accU[4][4][4];
#pragma unroll
    for (int mt = 0; mt < 4; mt++)
#pragma unroll
        for (int nt = 0; nt < 4; nt++)
#pragma unroll
            for (int i = 0; i < 4; i++) { accG[mt][nt][i] = 0.f; accU[mt][nt][i] = 0.f; }

    uint32_t aOff = (uint32_t)((mb + (lane & 15)) * 80 + (lane >> 4) * 16);
    uint32_t bOff = (uint32_t)((lane & 15) * 272 + (lane >> 4) * 16);

    for (int c = 0; c < NCH; c++) {
        if (c + 1 < NCH) asm volatile("cp.async.wait_group 1;" ::: "memory");
        else             asm volatile("cp.async.wait_group 0;" ::: "memory");
        __syncthreads();                 // all warps past iter c-1 compute; stage c ready
        if (c + 2 < NCH) ISSUE_A(c + 2, (c + 2) % 3);   // overlaps compute of stage c
        uint32_t stg = sb + 512 + (c % 3) * STG_A;
#pragma unroll
        for (int ks = 0; ks < 2; ks++) {
            uint32_t af[4][4];
#pragma unroll
            for (int mt = 0; mt < 4; mt++)
                ldsm4(af[mt], stg + aOff + mt * 16 * 80 + ks * 32);
            uint32_t bg[2][4], bu[2][4];
#pragma unroll
            for (int pr = 0; pr < 2; pr++) {
                uint32_t co = (uint32_t)((nb + pr * 16) * 2 + ks * 16 * 272);
                ldsm4t(bg[pr], stg + 10240 + bOff + co);
                ldsm4t(bu[pr], stg + 18944 + bOff + co);
            }
#pragma unroll
            for (int pr = 0; pr < 2; pr++)
#pragma unroll
                for (int hn = 0; hn < 2; hn++) {
                    int nt = pr * 2 + hn;
#pragma unroll
                    for (int mt = 0; mt < 4; mt++) {
                        mma_f16(accG[mt][nt], af[mt], bg[pr] + hn * 2);
                        mma_f16(accU[mt][nt], af[mt], bu[pr] + hn * 2);
                    }
                }
        }
    }

    // epilogue: silu(gate)*up -> g_h16
#pragma unroll
    for (int mt = 0; mt < 4; mt++)
#pragma unroll
        for (int half = 0; half < 2; half++) {
            int r = m0 + mb + mt * 16 + gid + half * 8;
            if (r < cnt) {
                __half* hp = g_h16 + (size_t)(base + r) * F_DIM + n0 + nb + tig * 2;
#pragma unroll
                for (int nt = 0; nt < 4; nt++) {
                    float h0 = silu_mul(accG[mt][nt][half * 2 + 0], accU[mt][nt][half * 2 + 0]);
                    float h1 = silu_mul(accG[mt][nt][half * 2 + 1], accU[mt][nt][half * 2 + 1]);
                    *(__half2*)(hp + nt * 8) = __floats2half2_rn(h0, h1);
                }
            }
        }
#undef ISSUE_A
}

// ================= pass B: out += w * (H1 Wd), fp16 mma + cp.async ================
// CTA 128M x 256N, BK=32; B rows 528B stride; 1 sync/iter.
__global__ void __launch_bounds__(256, 1)
gemmB_kernel(float* __restrict__ out) {
    int e = blockIdx.z;
    int cnt = g_count[e];
    int m0 = blockIdx.y * 128;
    if (m0 >= cnt) return;
    int base = g_off[e];
    int n0 = blockIdx.x * 256;

    extern __shared__ __align__(16) char dsm[];
    uint32_t sb = smem_u32(dsm);

    int tid = threadIdx.x, wid = tid >> 5, lane = tid & 31;
    int gid = lane >> 2, tig = lane & 3;
    int mb = (wid & 1) * 64;
    int nb = (wid >> 1) * 64;

    const __half* Wd = g_wd16 + (size_t)e * F_DIM * H_DIM + n0;

    int a_row[2], a_j[2], b_row[4], b_j[4];
#pragma unroll
    for (int i = 0; i < 2; i++) { int i2 = tid + i * 256; a_row[i] = i2 >> 2; a_j[i] = i2 & 3; }
#pragma unroll
    for (int i = 0; i < 4; i++) { int i2 = tid + i * 256; b_row[i] = i2 >> 5; b_j[i] = i2 & 31; }

    const int NCH = F_DIM / 32;  // 128
#define ISSUE_B(c, s)                                                                  \
    {                                                                                  \
        int k0 = (c) * 32;                                                             \
        uint32_t stg_i = sb + (s) * STG_B;                                             \
        _Pragma("unroll")                                                              \
        for (int i = 0; i < 2; i++) {                                                  \
            int r = m0 + a_row[i];                                                     \
            int ok = (r < cnt);                                                        \
            const __half* src = g_h16 + (size_t)(base + (ok ? r : 0)) * F_DIM + k0 + a_j[i] * 8; \
            cp16(stg_i + a_row[i] * 80 + a_j[i] * 16, src, ok ? 16u : 0u);             \
        }                                                                              \
        _Pragma("unroll")                                                              \
        for (int i = 0; i < 4; i++) {                                                  \
            cp16(stg_i + 10240 + b_row[i] * 528 + b_j[i] * 16,                         \
                 Wd + (size_t)(k0 + b_row[i]) * H_DIM + b_j[i] * 8, 16u);              \
        }                                                                              \
        cp_commit();                                                                   \
    }

    ISSUE_B(0, 0);
    ISSUE_B(1, 1);

    float acc[4][8][4];
#pragma unroll
    for (int mt = 0; mt < 4; mt++)
#pragma unroll
        for (int nt = 0; nt < 8; nt++)
#pragma unroll
            for (int i = 0; i < 4; i++) acc[mt][nt][i] = 0.f;

    uint32_t aOff = (uint32_t)((mb + (lane & 15)) * 80 + (lane >> 4) * 16);
    uint32_t bOff = (uint32_t)((lane & 15) * 528 + (lane >> 4) * 16);

    for (int c = 0; c < NCH; c++) {
        if (c + 1 < NCH) asm volatile("cp.async.wait_group 1;" ::: "memory");
        else             asm volatile("cp.async.wait_group 0;" ::: "memory");
        __syncthreads();
        if (c + 2 < NCH) ISSUE_B(c + 2, (c + 2) % 3);
        uint32_t stg = sb + (c % 3) * STG_B;
#pragma unroll
        for (int ks = 0; ks < 2; ks++) {
            uint32_t af[4][4];
#pragma unroll
            for (int mt = 0; mt < 4; mt++)
                ldsm4(af[mt], stg + aOff + mt * 16 * 80 + ks * 32);
            uint32_t bf[4][4];
#pragma unroll
            for (int pr = 0; pr < 4; pr++) {
                uint32_t co = (uint32_t)((nb + pr * 16) * 2 + ks * 16 * 528);
                ldsm4t(bf[pr], stg + 10240 + bOff + co);
            }
#pragma unroll
            for (int pr = 0; pr < 4; pr++)
#pragma unroll
                for (int hn = 0; hn < 2; hn++) {
                    int nt = pr * 2 + hn;
#pragma unroll
                    for (int mt = 0; mt < 4; mt++)
                        mma_f16(acc[mt][nt], af[mt], bf[pr] + hn * 2);
                }
        }
    }

    // epilogue: weighted atomic combine
#pragma unroll
    for (int mt = 0; mt < 4; mt++)
#pragma unroll
        for (int half = 0; half < 2; half++) {
            int r = m0 + mb + mt * 16 + gid + half * 8;
            if (r < cnt) {
                int tok = g_slot_tok[base + r];
                float w = g_slot_w[base + r];
                float* op = out + (size_t)tok * H_DIM + n0 + nb + tig * 2;
#pragma unroll
                for (int nt = 0; nt < 8; nt++) {
                    atomicAdd(op + nt * 8 + 0, w * acc[mt][nt][half * 2 + 0]);
                    atomicAdd(op + nt * 8 + 1, w * acc[mt][nt][half * 2 + 1]);
                }
            }
        }
#undef ISSUE_B
}

// ---------------- launch ----------------
extern "C" void kernel_launch(void* const* d_in, const int* in_sizes, int n_in,
                              void* d_out, int out_size) {
    const float* x  = (const float*)d_in[0];
    const float* gw = (const float*)d_in[1];
    const float* wg = (const float*)d_in[2];
    const float* wu = (const float*)d_in[3];
    const float* wd = (const float*)d_in[4];
    float* out = (float*)d_out;

    cudaFuncSetAttribute(gemmA_kernel, cudaFuncAttributeMaxDynamicSharedMemorySize, SMEM_A_BYTES);
    cudaFuncSetAttribute(gemmB_kernel, cudaFuncAttributeMaxDynamicSharedMemorySize, SMEM_B_BYTES);

    init_kernel<<<512, 256>>>(out, out_size);

    __half* dg; __half* du; __half* dd;
    cudaGetSymbolAddress((void**)&dg, g_wg16);
    cudaGetSymbolAddress((void**)&du, g_wu16);
    cudaGetSymbolAddress((void**)&dd, g_wd16);
    const int NW = E_NUM * H_DIM * F_DIM;
    conv_kernel<<<NW / 1024, 256>>>(wg, dg, NW);
    conv_kernel<<<NW / 1024, 256>>>(wu, du, NW);
    conv_kernel<<<NW / 1024, 256>>>(wd, dd, NW);

    router_kernel<<<T_TOK / 8, 256>>>(x, gw);   // also writes g_x16
    offsets_kernel<<<1, 1>>>();
    scatter_kernel<<<T_TOK / 256, 256>>>();
    reduce_kernel<<<1, 256>>>(out, out_size);

    dim3 gA(F_DIM / 128, N_SLOTS / 128, E_NUM);
    gemmA_kernel<<<gA, 256, SMEM_A_BYTES>>>();

    dim3 gB(H_DIM / 256, N_SLOTS / 128, E_NUM);
    gemmB_kernel<<<gB, 256, SMEM_B_BYTES>>>(out);
}

// round 7
// speedup vs baseline: 7.8623x; 1.0166x over previous
#include <cuda_runtime.h>
#include <cuda_fp16.h>
#include <math.h>
#include <stdint.h>

#define T_TOK 8192
#define H_DIM 1024
#define F_DIM 4096
#define E_NUM 8
#define N_SLOTS (T_TOK * 2)

// ---------------- scratch (device globals; no runtime allocation) ----------------
__device__ float g_probs[T_TOK * E_NUM];
__device__ float g_lse2[T_TOK];
__device__ int   g_tok_e[T_TOK * 2];
__device__ float g_tok_w[T_TOK * 2];
__device__ int   g_count[E_NUM];
__device__ int   g_off[E_NUM + 1];
__device__ int   g_cursor[E_NUM];
__device__ int   g_slot_tok[N_SLOTS];
__device__ float g_slot_w[N_SLOTS];

__device__ __half g_x16[(size_t)T_TOK * H_DIM];
__device__ __half g_wg16[(size_t)E_NUM * H_DIM * F_DIM];
__device__ __half g_wu16[(size_t)E_NUM * H_DIM * F_DIM];
__device__ __half g_wd16[(size_t)E_NUM * F_DIM * H_DIM];
__device__ __half g_h16[(size_t)N_SLOTS * F_DIM];   // 128 MB fp16 intermediate

// ---------------- PTX helpers ----------------
__device__ __forceinline__ uint32_t smem_u32(const void* p) {
    uint32_t a;
    asm("{ .reg .u64 t; cvta.to.shared.u64 t, %1; cvt.u32.u64 %0, t; }" : "=r"(a) : "l"(p));
    return a;
}
__device__ __forceinline__ void cp16(uint32_t dst, const void* src, uint32_t sz) {
    asm volatile("cp.async.cg.shared.global [%0], [%1], 16, %2;"
                 :: "r"(dst), "l"(__cvta_generic_to_global(src)), "r"(sz) : "memory");
}
__device__ __forceinline__ void cp_commit() {
    asm volatile("cp.async.commit_group;" ::: "memory");
}
__device__ __forceinline__ void ldsm4(uint32_t* r, uint32_t a) {
    asm volatile("ldmatrix.sync.aligned.m8n8.x4.shared.b16 {%0,%1,%2,%3}, [%4];"
                 : "=r"(r[0]), "=r"(r[1]), "=r"(r[2]), "=r"(r[3]) : "r"(a));
}
__device__ __forceinline__ void ldsm4t(uint32_t* r, uint32_t a) {
    asm volatile("ldmatrix.sync.aligned.m8n8.x4.trans.shared.b16 {%0,%1,%2,%3}, [%4];"
                 : "=r"(r[0]), "=r"(r[1]), "=r"(r[2]), "=r"(r[3]) : "r"(a));
}
__device__ __forceinline__ void mma_f16(float* c, const uint32_t* a, const uint32_t* b) {
    asm volatile("mma.sync.aligned.m16n8k16.row.col.f32.f16.f16.f32 "
                 "{%0,%1,%2,%3}, {%4,%5,%6,%7}, {%8,%9}, {%0,%1,%2,%3};"
                 : "+f"(c[0]), "+f"(c[1]), "+f"(c[2]), "+f"(c[3])
                 : "r"(a[0]), "r"(a[1]), "r"(a[2]), "r"(a[3]), "r"(b[0]), "r"(b[1]));
}
__device__ __forceinline__ float silu_mul(float g, float u) {
    return g / (1.f + __expf(-g)) * u;
}

// ---------------- init ----------------
__global__ void init_kernel(float* out, int n) {
    int tid = blockIdx.x * blockDim.x + threadIdx.x;
    if (tid < E_NUM) { g_count[tid] = 0; g_cursor[tid] = 0; }
    for (int i = tid; i < n; i += gridDim.x * blockDim.x) out[i] = 0.f;
}

// ---------------- fp32 -> fp16 conversion (all 3 weight tensors, one launch) ----------------
__global__ void conv3_kernel(const float* __restrict__ wg, const float* __restrict__ wu,
                             const float* __restrict__ wd,
                             __half* __restrict__ dg, __half* __restrict__ du,
                             __half* __restrict__ dd, int n) {
    const float* s = (blockIdx.y == 0) ? wg : (blockIdx.y == 1) ? wu : wd;
    __half* d = (blockIdx.y == 0) ? dg : (blockIdx.y == 1) ? du : dd;
    int i = (blockIdx.x * 256 + threadIdx.x) * 4;
    if (i >= n) return;
    float4 v = *(const float4*)(s + i);
    union { __half2 h[2]; uint2 u; } pk;
    pk.h[0] = __floats2half2_rn(v.x, v.y);
    pk.h[1] = __floats2half2_rn(v.z, v.w);
    *(uint2*)(d + i) = pk.u;
}

// ---------------- router: one warp per token (also emits x as fp16) ----------------
__global__ void router_kernel(const float* __restrict__ x, const float* __restrict__ gw) {
    __shared__ float sgw[H_DIM * E_NUM];
    for (int i = threadIdx.x; i < H_DIM * E_NUM; i += blockDim.x) sgw[i] = gw[i];
    __syncthreads();

    int warp = threadIdx.x >> 5;
    int lane = threadIdx.x & 31;
    int t = blockIdx.x * (blockDim.x >> 5) + warp;
    if (t >= T_TOK) return;

    const float* xr = x + (size_t)t * H_DIM;
    float acc[E_NUM];
#pragma unroll
    for (int e = 0; e < E_NUM; e++) acc[e] = 0.f;
    for (int h = lane; h < H_DIM; h += 32) {
        float xv = xr[h];
#pragma unroll
        for (int e = 0; e < E_NUM; e++) acc[e] += xv * sgw[h * E_NUM + e];
    }

    {
        __half* dx = g_x16 + (size_t)t * H_DIM;
#pragma unroll
        for (int k = 0; k < H_DIM / 4 / 32; k++) {
            int idx = (lane + k * 32) * 4;
            float4 v = *(const float4*)(xr + idx);
            union { __half2 h[2]; uint2 u; } pk;
            pk.h[0] = __floats2half2_rn(v.x, v.y);
            pk.h[1] = __floats2half2_rn(v.z, v.w);
            *(uint2*)(dx + idx) = pk.u;
        }
    }

#pragma unroll
    for (int off = 16; off; off >>= 1)
#pragma unroll
        for (int e = 0; e < E_NUM; e++) acc[e] += __shfl_xor_sync(0xffffffffu, acc[e], off);

    if (lane == 0) {
        float m = acc[0];
#pragma unroll
        for (int e = 1; e < E_NUM; e++) m = fmaxf(m, acc[e]);
        float p[E_NUM], s = 0.f;
#pragma unroll
        for (int e = 0; e < E_NUM; e++) { p[e] = expf(acc[e] - m); s += p[e]; }
        float lse = m + logf(s);
        g_lse2[t] = lse * lse;
        float inv = 1.f / s;
#pragma unroll
        for (int e = 0; e < E_NUM; e++) { p[e] *= inv; g_probs[t * E_NUM + e] = p[e]; }
        int i1 = 0;
#pragma unroll
        for (int e = 1; e < E_NUM; e++) if (p[e] > p[i1]) i1 = e;
        int i2 = (i1 == 0) ? 1 : 0;
#pragma unroll
        for (int e = 0; e < E_NUM; e++) if (e != i1 && p[e] > p[i2]) i2 = e;
        float w1 = p[i1], w2 = p[i2];
        float ws = 1.f / (w1 + w2);
        g_tok_e[2 * t + 0] = i1;  g_tok_w[2 * t + 0] = w1 * ws;
        g_tok_e[2 * t + 1] = i2;  g_tok_w[2 * t + 1] = w2 * ws;
        atomicAdd(&g_count[i1], 1);
        atomicAdd(&g_count[i2], 1);
    }
}

__global__ void offsets_kernel() {
    g_off[0] = 0;
    for (int e = 0; e < E_NUM; e++) g_off[e + 1] = g_off[e] + g_count[e];
}

__global__ void scatter_kernel() {
    int t = blockIdx.x * blockDim.x + threadIdx.x;
    if (t >= T_TOK) return;
#pragma unroll
    for (int k = 0; k < 2; k++) {
        int e = g_tok_e[2 * t + k];
        int pos = g_off[e] + atomicAdd(&g_cursor[e], 1);
        g_slot_tok[pos] = t;
        g_slot_w[pos] = g_tok_w[2 * t + k];
    }
}

__global__ void reduce_kernel(float* out, int out_size) {
    __shared__ float sp[256 * E_NUM];
    __shared__ float sl[256];
    int tid = threadIdx.x;
    float lp[E_NUM];
#pragma unroll
    for (int e = 0; e < E_NUM; e++) lp[e] = 0.f;
    float ll = 0.f;
    for (int t = tid; t < T_TOK; t += 256) {
#pragma unroll
        for (int e = 0; e < E_NUM; e++) lp[e] += g_probs[t * E_NUM + e];
        ll += g_lse2[t];
    }
#pragma unroll
    for (int e = 0; e < E_NUM; e++) sp[tid * E_NUM + e] = lp[e];
    sl[tid] = ll;
    __syncthreads();
    for (int s = 128; s; s >>= 1) {
        if (tid < s) {
#pragma unroll
            for (int e = 0; e < E_NUM; e++) sp[tid * E_NUM + e] += sp[(tid + s) * E_NUM + e];
            sl[tid] += sl[tid + s];
        }
        __syncthreads();
    }
    if (tid == 0) {
        float bal = 0.f;
        for (int e = 0; e < E_NUM; e++) {
            float frac = (float)g_count[e] / (float)(T_TOK * 2);
            float meanp = sp[e] / (float)T_TOK;
            bal += frac * meanp;
        }
        out[out_size - 2] = bal * (float)E_NUM;
        out[out_size - 1] = sl[0] / (float)T_TOK;
    }
}

// ================= pass A: h = silu(X Wg)*(X Wu), fp16 mma, 512 threads ================
// CTA 128M x 128N(gate)+128N(up), BK=32, 16 warps, warp tile 32x32 (both matrices).
// SMEM strides (bytes): A rows 80, B rows 272. 3-stage cp.async, 1 sync/iter.
#define STG_A 27648
#define SMEM_A_BYTES (512 + 3 * STG_A)
#define STG_B 27136
#define SMEM_B_BYTES (3 * STG_B)

__global__ void __launch_bounds__(512, 1)
gemmA_kernel() {
    int e = blockIdx.z;
    int cnt = g_count[e];
    int m0 = blockIdx.y * 128;
    if (m0 >= cnt) return;
    int base = g_off[e];
    int n0 = blockIdx.x * 128;

    extern __shared__ __align__(16) char dsm[];
    int* toks = (int*)dsm;
    uint32_t sb = smem_u32(dsm);

    int tid = threadIdx.x, wid = tid >> 5, lane = tid & 31;
    int gid = lane >> 2, tig = lane & 3;
    int mb = (wid & 3) * 32;
    int nb = (wid >> 2) * 32;

    if (tid < 128) {
        int idx = m0 + tid;
        toks[tid] = (idx < cnt) ? g_slot_tok[base + idx] : -1;
    }
    __syncthreads();

    const __half* Wg = g_wg16 + (size_t)e * H_DIM * F_DIM + n0;
    const __half* Wu = g_wu16 + (size_t)e * H_DIM * F_DIM + n0;

    // staging: 512 threads -> A 1 copy (128r x 4 slots), B 1 copy each (32r x 16 slots)
    int a_row = tid >> 2, a_j = tid & 3;
    int b_row = tid >> 4, b_j = tid & 15;

    const int NCH = H_DIM / 32;  // 32
#define ISSUE_A(c, s)                                                                  \
    {                                                                                  \
        int k0 = (c) * 32;                                                             \
        uint32_t stg_i = sb + 512 + (s) * STG_A;                                       \
        int tok = toks[a_row];                                                         \
        const __half* src = g_x16 + (size_t)(tok < 0 ? 0 : tok) * H_DIM + k0 + a_j * 8;\
        cp16(stg_i + a_row * 80 + a_j * 16, src, tok >= 0 ? 16u : 0u);                 \
        cp16(stg_i + 10240 + b_row * 272 + b_j * 16,                                   \
             Wg + (size_t)(k0 + b_row) * F_DIM + b_j * 8, 16u);                        \
        cp16(stg_i + 18944 + b_row * 272 + b_j * 16,                                   \
             Wu + (size_t)(k0 + b_row) * F_DIM + b_j * 8, 16u);                        \
        cp_commit();                                                                   \
    }

    ISSUE_A(0, 0);
    ISSUE_A(1, 1);

    float accG[2][4][4], accU[2][4][4];
#pragma unroll
    for (int mt = 0; mt < 2; mt++)
#pragma unroll
        for (int nt = 0; nt < 4; nt++)
#pragma unroll
            for (int i = 0; i < 4; i++) { accG[mt][nt][i] = 0.f; accU[mt][nt][i] = 0.f; }

    uint32_t aOff = (uint32_t)((mb + (lane & 15)) * 80 + (lane >> 4) * 16);
    uint32_t bOff = (uint32_t)((lane & 15) * 272 + (lane >> 4) * 16);

    for (int c = 0; c < NCH; c++) {
        if (c + 1 < NCH) asm volatile("cp.async.wait_group 1;" ::: "memory");
        else             asm volatile("cp.async.wait_group 0;" ::: "memory");
        __syncthreads();
        if (c + 2 < NCH) ISSUE_A(c + 2, (c + 2) % 3);
        uint32_t stg = sb + 512 + (c % 3) * STG_A;
#pragma unroll
        for (int ks = 0; ks < 2; ks++) {
            uint32_t af[2][4];
#pragma unroll
            for (int mt = 0; mt < 2; mt++)
                ldsm4(af[mt], stg + aOff + mt * 16 * 80 + ks * 32);
            uint32_t bg[2][4], bu[2][4];
#pragma unroll
            for (int pr = 0; pr < 2; pr++) {
                uint32_t co = (uint32_t)((nb + pr * 16) * 2 + ks * 16 * 272);
                ldsm4t(bg[pr], stg + 10240 + bOff + co);
                ldsm4t(bu[pr], stg + 18944 + bOff + co);
            }
#pragma unroll
            for (int pr = 0; pr < 2; pr++)
#pragma unroll
                for (int hn = 0; hn < 2; hn++) {
                    int nt = pr * 2 + hn;
#pragma unroll
                    for (int mt = 0; mt < 2; mt++) {
                        mma_f16(accG[mt][nt], af[mt], bg[pr] + hn * 2);
                        mma_f16(accU[mt][nt], af[mt], bu[pr] + hn * 2);
                    }
                }
        }
    }

    // epilogue: silu(gate)*up -> g_h16
#pragma unroll
    for (int mt = 0; mt < 2; mt++)
#pragma unroll
        for (int half = 0; half < 2; half++) {
            int r = m0 + mb + mt * 16 + gid + half * 8;
            if (r < cnt) {
                __half* hp = g_h16 + (size_t)(base + r) * F_DIM + n0 + nb + tig * 2;
#pragma unroll
                for (int nt = 0; nt < 4; nt++) {
                    float h0 = silu_mul(accG[mt][nt][half * 2 + 0], accU[mt][nt][half * 2 + 0]);
                    float h1 = silu_mul(accG[mt][nt][half * 2 + 1], accU[mt][nt][half * 2 + 1]);
                    *(__half2*)(hp + nt * 8) = __floats2half2_rn(h0, h1);
                }
            }
        }
#undef ISSUE_A
}

// ================= pass B: out += w * (H1 Wd), fp16 mma, 512 threads ================
// CTA 128M x 256N, BK=32, 16 warps, warp tile 32x64. B rows 528B stride.
__global__ void __launch_bounds__(512, 1)
gemmB_kernel(float* __restrict__ out) {
    int e = blockIdx.z;
    int cnt = g_count[e];
    int m0 = blockIdx.y * 128;
    if (m0 >= cnt) return;
    int base = g_off[e];
    int n0 = blockIdx.x * 256;

    extern __shared__ __align__(16) char dsm[];
    uint32_t sb = smem_u32(dsm);

    int tid = threadIdx.x, wid = tid >> 5, lane = tid & 31;
    int gid = lane >> 2, tig = lane & 3;
    int mb = (wid & 3) * 32;
    int nb = (wid >> 2) * 64;

    const __half* Wd = g_wd16 + (size_t)e * F_DIM * H_DIM + n0;

    int a_row = tid >> 2, a_j = tid & 3;
    int b_row[2], b_j[2];
#pragma unroll
    for (int i = 0; i < 2; i++) { int i2 = tid + i * 512; b_row[i] = i2 >> 5; b_j[i] = i2 & 31; }

    const int NCH = F_DIM / 32;  // 128
#define ISSUE_B(c, s)                                                                  \
    {                                                                                  \
        int k0 = (c) * 32;                                                             \
        uint32_t stg_i = sb + (s) * STG_B;                                             \
        int r = m0 + a_row;                                                            \
        int ok = (r < cnt);                                                            \
        const __half* src = g_h16 + (size_t)(base + (ok ? r : 0)) * F_DIM + k0 + a_j * 8; \
        cp16(stg_i + a_row * 80 + a_j * 16, src, ok ? 16u : 0u);                       \
        _Pragma("unroll")                                                              \
        for (int i = 0; i < 2; i++) {                                                  \
            cp16(stg_i + 10240 + b_row[i] * 528 + b_j[i] * 16,                         \
                 Wd + (size_t)(k0 + b_row[i]) * H_DIM + b_j[i] * 8, 16u);              \
        }                                                                              \
        cp_commit();                                                                   \
    }

    ISSUE_B(0, 0);
    ISSUE_B(1, 1);

    float acc[2][8][4];
#pragma unroll
    for (int mt = 0; mt < 2; mt++)
#pragma unroll
        for (int nt = 0; nt < 8; nt++)
#pragma unroll
            for (int i = 0; i < 4; i++) acc[mt][nt][i] = 0.f;

    uint32_t aOff = (uint32_t)((mb + (lane & 15)) * 80 + (lane >> 4) * 16);
    uint32_t bOff = (uint32_t)((lane & 15) * 528 + (lane >> 4) * 16);

    for (int c = 0; c < NCH; c++) {
        if (c + 1 < NCH) asm volatile("cp.async.wait_group 1;" ::: "memory");
        else             asm volatile("cp.async.wait_group 0;" ::: "memory");
        __syncthreads();
        if (c + 2 < NCH) ISSUE_B(c + 2, (c + 2) % 3);
        uint32_t stg = sb + (c % 3) * STG_B;
#pragma unroll
        for (int ks = 0; ks < 2; ks++) {
            uint32_t af[2][4];
#pragma unroll
            for (int mt = 0; mt < 2; mt++)
                ldsm4(af[mt], stg + aOff + mt * 16 * 80 + ks * 32);
            uint32_t bf[4][4];
#pragma unroll
            for (int pr = 0; pr < 4; pr++) {
                uint32_t co = (uint32_t)((nb + pr * 16) * 2 + ks * 16 * 528);
                ldsm4t(bf[pr], stg + 10240 + bOff + co);
            }
#pragma unroll
            for (int pr = 0; pr < 4; pr++)
#pragma unroll
                for (int hn = 0; hn < 2; hn++) {
                    int nt = pr * 2 + hn;
#pragma unroll
                    for (int mt = 0; mt < 2; mt++)
                        mma_f16(acc[mt][nt], af[mt], bf[pr] + hn * 2);
                }
        }
    }

    // epilogue: weighted atomic combine
#pragma unroll
    for (int mt = 0; mt < 2; mt++)
#pragma unroll
        for (int half = 0; half < 2; half++) {
            int r = m0 + mb + mt * 16 + gid + half * 8;
            if (r < cnt) {
                int tok = g_slot_tok[base + r];
                float w = g_slot_w[base + r];
                float* op = out + (size_t)tok * H_DIM + n0 + nb + tig * 2;
#pragma unroll
                for (int nt = 0; nt < 8; nt++) {
                    atomicAdd(op + nt * 8 + 0, w * acc[mt][nt][half * 2 + 0]);
                    atomicAdd(op + nt * 8 + 1, w * acc[mt][nt][half * 2 + 1]);
                }
            }
        }
#undef ISSUE_B
}

// ---------------- launch ----------------
extern "C" void kernel_launch(void* const* d_in, const int* in_sizes, int n_in,
                              void* d_out, int out_size) {
    const float* x  = (const float*)d_in[0];
    const float* gw = (const float*)d_in[1];
    const float* wg = (const float*)d_in[2];
    const float* wu = (const float*)d_in[3];
    const float* wd = (const float*)d_in[4];
    float* out = (float*)d_out;

    cudaFuncSetAttribute(gemmA_kernel, cudaFuncAttributeMaxDynamicSharedMemorySize, SMEM_A_BYTES);
    cudaFuncSetAttribute(gemmB_kernel, cudaFuncAttributeMaxDynamicSharedMemorySize, SMEM_B_BYTES);

    init_kernel<<<512, 256>>>(out, out_size);

    __half* dg; __half* du; __half* dd;
    cudaGetSymbolAddress((void**)&dg, g_wg16);
    cudaGetSymbolAddress((void**)&du, g_wu16);
    cudaGetSymbolAddress((void**)&dd, g_wd16);
    const int NW = E_NUM * H_DIM * F_DIM;
    dim3 gC(NW / 1024, 3);
    conv3_kernel<<<gC, 256>>>(wg, wu, wd, dg, du, dd, NW);

    router_kernel<<<T_TOK / 8, 256>>>(x, gw);   // also writes g_x16
    offsets_kernel<<<1, 1>>>();
    scatter_kernel<<<T_TOK / 256, 256>>>();
    reduce_kernel<<<1, 256>>>(out, out_size);

    dim3 gA(F_DIM / 128, N_SLOTS / 128, E_NUM);
    gemmA_kernel<<<gA, 512, SMEM_A_BYTES>>>();

    dim3 gB(H_DIM / 256, N_SLOTS / 128, E_NUM);
    gemmB_kernel<<<gB, 512, SMEM_B_BYTES>>>(out);
}